// round 4
// baseline (speedup 1.0000x reference)
#include <cuda_runtime.h>
#include <cuda_bf16.h>
#include <math.h>

// Problem constants
#define NB   8
#define C    512
#define HI   32
#define HO   64
#define PIX  (HO*HO)       // 4096

// Scratch (device globals; no runtime allocation allowed)
__device__ float g_h1[(size_t)NB * C * HO * HO];   // 64 MB: output of up-conv stage
__device__ float g_wsq_up[C * C];                  // [i][o] sum_t up_w^2
__device__ float g_wsq_cT[C * C];                  // [i][o] sum_t c_w^2 (transposed)
__device__ float g_s[3 * NB * C];                  // 0: up, 1: c, 2: rgb
__device__ float g_sigma[2 * NB * C];              // 0: up, 1: c

// ---------------------------------------------------------------------------
// K0: per-(in,out)-channel weight-square tap sums
// ---------------------------------------------------------------------------
__global__ void k_wsq(const float* __restrict__ up_w, const float* __restrict__ c_w) {
    int idx = blockIdx.x * blockDim.x + threadIdx.x;   // 0 .. 2*262144
    int which = idx >> 18;
    int p = idx & 262143;
    int i = p >> 9, o = p & 511;
    const float* src = which == 0 ? (up_w + ((i << 9) + o) * 9)
                                  : (c_w + ((o << 9) + i) * 9);
    float s = 0.f;
#pragma unroll
    for (int t = 0; t < 9; t++) s += src[t] * src[t];
    if (which == 0) g_wsq_up[p] = s;
    else            g_wsq_cT[p] = s;
}

// ---------------------------------------------------------------------------
// K1: style vectors s = v @ SW + SB  (3 matrices)
// ---------------------------------------------------------------------------
__global__ void k_style(const float* __restrict__ v,
                        const float* __restrict__ up_sw, const float* __restrict__ up_sb,
                        const float* __restrict__ c_sw,  const float* __restrict__ c_sb,
                        const float* __restrict__ rgb_sw,const float* __restrict__ rgb_sb) {
    int m = blockIdx.y, n = blockIdx.x, i = threadIdx.x;   // 512 threads
    __shared__ float sv[C];
    sv[i] = v[n * C + i];
    __syncthreads();
    const float* SW = (m == 0) ? up_sw : (m == 1) ? c_sw : rgb_sw;
    const float* SB = (m == 0) ? up_sb : (m == 1) ? c_sb : rgb_sb;
    float acc = SB[i];
#pragma unroll 4
    for (int l = 0; l < C; l++) acc = fmaf(sv[l], SW[l * C + i], acc);
    g_s[(m * NB + n) * C + i] = acc;
}

// ---------------------------------------------------------------------------
// K2: demod sigma = sqrt(sum_i s_i^2 * wsq[i][o] + 1e-8)
// ---------------------------------------------------------------------------
__global__ void k_sigma(void) {
    int m = blockIdx.y, n = blockIdx.x, o = threadIdx.x;   // 512 threads
    __shared__ float s2[C];
    float sv = g_s[(m * NB + n) * C + o];
    s2[o] = sv * sv;
    __syncthreads();
    const float* wsq = (m == 0) ? g_wsq_up : g_wsq_cT;
    float acc = 1e-8f;
#pragma unroll 4
    for (int i = 0; i < C; i++) acc = fmaf(s2[i], wsq[i * C + o], acc);
    g_sigma[(m * NB + n) * C + o] = sqrtf(acc);
}

// ---------------------------------------------------------------------------
// K3: modulated transposed conv 3x3, stride 2 (subpixel decomposition)
//   out(2a,2b)     = sum_i in[a,b]*W[1][1]
//   out(2a,2b+1)   = in[a,b+1]*W[1][0] + in[a,b]*W[1][2]
//   out(2a+1,2b)   = in[a+1,b]*W[0][1] + in[a,b]*W[2][1]
//   out(2a+1,2b+1) = in[a+1,b+1]*W[0][0] + in[a+1,b]*W[0][2]
//                  + in[a,b+1]*W[2][0]   + in[a,b]*W[2][2]
// Epilogue: /sigma_up + bias + ns*noise1, LeakyReLU(0.2) -> g_h1
// Block: 64 oc x (4a x 8b input positions) = 8x16 output tile, 256 threads
// ---------------------------------------------------------------------------
#define CC2 16
__global__ __launch_bounds__(256, 2)
void k_upconv(const float* __restrict__ x, const float* __restrict__ up_w,
              const float* __restrict__ up_b, const float* __restrict__ noise1,
              const float* __restrict__ nsp) {
    __shared__ float sIn[CC2][5][9];
    __shared__ float sW[CC2 * 64 * 9];   // [ci][oc][t]

    const int n = blockIdx.z;
    const int ocBase = blockIdx.y * 64;
    const int a0 = (blockIdx.x >> 2) * 4;
    const int b0 = (blockIdx.x & 3) * 8;
    const int tid = threadIdx.x;
    const int ocg = tid >> 4;          // 0..15, 4 oc each
    const int pos = tid & 15;
    const int arB = pos >> 3;          // 0..1
    const int bc  = pos & 7;           // 0..7

    float acc[4][2][4];
#pragma unroll
    for (int j = 0; j < 4; j++)
#pragma unroll
        for (int p = 0; p < 2; p++)
#pragma unroll
            for (int s = 0; s < 4; s++) acc[j][p][s] = 0.f;

    for (int ci0 = 0; ci0 < C; ci0 += CC2) {
        __syncthreads();
        // input tile (scaled by style) with zero pad at row/col 32
        for (int e = tid; e < CC2 * 45; e += 256) {
            int ci = e / 45, r = e % 45, ar = r / 9, bx = r % 9;
            int gy = a0 + ar, gx = b0 + bx;
            float vv = 0.f;
            if (gy < HI && gx < HI)
                vv = x[((n * C + ci0 + ci) * HI + gy) * HI + gx]
                     * g_s[(0 * NB + n) * C + ci0 + ci];
            sIn[ci][ar][bx] = vv;
        }
        // weights: up_w[i][o][t], per-ci contiguous 576-float run
        for (int e = tid; e < CC2 * 576; e += 256) {
            int ci = e / 576, r = e % 576;
            sW[ci * 576 + r] = up_w[(ci0 + ci) * (C * 9) + ocBase * 9 + r];
        }
        __syncthreads();

#pragma unroll 2
        for (int ci = 0; ci < CC2; ci++) {
            float w[4][9];
#pragma unroll
            for (int j = 0; j < 4; j++)
#pragma unroll
                for (int t = 0; t < 9; t++)
                    w[j][t] = sW[ci * 576 + (ocg * 4 + j) * 9 + t];
#pragma unroll
            for (int p = 0; p < 2; p++) {
                int ar = arB + 2 * p;
                float x00 = sIn[ci][ar][bc];
                float x01 = sIn[ci][ar][bc + 1];
                float x10 = sIn[ci][ar + 1][bc];
                float x11 = sIn[ci][ar + 1][bc + 1];
#pragma unroll
                for (int j = 0; j < 4; j++) {
                    acc[j][p][0] = fmaf(x00, w[j][4], acc[j][p][0]);
                    acc[j][p][1] = fmaf(x01, w[j][3], fmaf(x00, w[j][5], acc[j][p][1]));
                    acc[j][p][2] = fmaf(x10, w[j][1], fmaf(x00, w[j][7], acc[j][p][2]));
                    acc[j][p][3] = fmaf(x11, w[j][0], fmaf(x10, w[j][2],
                                   fmaf(x01, w[j][6], fmaf(x00, w[j][8], acc[j][p][3]))));
                }
            }
        }
    }

    const float ns = nsp[0];
#pragma unroll
    for (int j = 0; j < 4; j++) {
        int oc = ocBase + ocg * 4 + j;
        float sig = g_sigma[(0 * NB + n) * C + oc];
        float inv = 1.f / sig;
        float bias = up_b[oc];
#pragma unroll
        for (int p = 0; p < 2; p++) {
            int a = a0 + arB + 2 * p;
            int b = b0 + bc;
#pragma unroll
            for (int s = 0; s < 4; s++) {
                int y = 2 * a + (s >> 1);
                int xx = 2 * b + (s & 1);
                float vv = acc[j][p][s] * inv + bias;
                vv += ns * noise1[n * PIX + y * HO + xx];
                vv = vv > 0.f ? vv : 0.2f * vv;
                g_h1[((size_t)(n * C + oc) * HO + y) * HO + xx] = vv;
            }
        }
    }
}

// ---------------------------------------------------------------------------
// K4: modulated 3x3 conv, pad 1, with demod; epilogue noise2 + lrelu -> d_out(h)
// Block: 64 oc x (8y x 16x) output tile, 256 threads, per-thread 4oc x 8x
// ---------------------------------------------------------------------------
#define CC4 8
__global__ __launch_bounds__(256, 2)
void k_conv3(const float* __restrict__ c_w, const float* __restrict__ c_b,
             const float* __restrict__ noise2, const float* __restrict__ nsp,
             float* __restrict__ out) {
    __shared__ float sIn[CC4][10][18];
    __shared__ float sW[CC4 * 64 * 9];   // [ci][oc][t]

    const int n = blockIdx.z;
    const int ocBase = blockIdx.y * 64;
    const int y0 = (blockIdx.x >> 2) * 8;
    const int x0 = (blockIdx.x & 3) * 16;
    const int tid = threadIdx.x;
    const int row = tid >> 5;            // 0..7 (one warp per row)
    const int xg  = (tid >> 4) & 1;      // 0..1
    const int ocg = tid & 15;            // 0..15, oc = ocBase + ocg + 16*j

    float acc[4][8];
#pragma unroll
    for (int j = 0; j < 4; j++)
#pragma unroll
        for (int xx = 0; xx < 8; xx++) acc[j][xx] = 0.f;

    for (int ci0 = 0; ci0 < C; ci0 += CC4) {
        __syncthreads();
        // input halo tile (scaled by style), zero-padded
        for (int e = tid; e < CC4 * 180; e += 256) {
            int ci = e / 180, r = e % 180, ry = r / 18, rx = r % 18;
            int gy = y0 - 1 + ry, gx = x0 - 1 + rx;
            float vv = 0.f;
            if (gy >= 0 && gy < HO && gx >= 0 && gx < HO)
                vv = g_h1[((size_t)(n * C + ci0 + ci) * HO + gy) * HO + gx]
                     * g_s[(1 * NB + n) * C + ci0 + ci];
            sIn[ci][ry][rx] = vv;
        }
        // weights: c_w[o][i][t]; per-oc contiguous 72-float run for this ci chunk
        for (int e = tid; e < CC4 * 576; e += 256) {
            int oc = e / 72, r = e % 72;
            int ci = r / 9, t = r % 9;
            sW[ci * 576 + oc * 9 + t] =
                c_w[(ocBase + oc) * (C * 9) + ci0 * 9 + r];
        }
        __syncthreads();

#pragma unroll 1
        for (int ci = 0; ci < CC4; ci++) {
            float w[4][9];
#pragma unroll
            for (int j = 0; j < 4; j++)
#pragma unroll
                for (int t = 0; t < 9; t++)
                    w[j][t] = sW[ci * 576 + (ocg + 16 * j) * 9 + t];
#pragma unroll
            for (int dy = 0; dy < 3; dy++) {
                float r_[10];
                const float* base = &sIn[ci][row + dy][xg * 8];
#pragma unroll
                for (int k = 0; k < 10; k++) r_[k] = base[k];
#pragma unroll
                for (int xx = 0; xx < 8; xx++) {
#pragma unroll
                    for (int j = 0; j < 4; j++) {
                        acc[j][xx] = fmaf(r_[xx],     w[j][dy * 3 + 0],
                                     fmaf(r_[xx + 1], w[j][dy * 3 + 1],
                                     fmaf(r_[xx + 2], w[j][dy * 3 + 2], acc[j][xx])));
                    }
                }
            }
        }
    }

    const float ns = nsp[0];
    const int y = y0 + row;
#pragma unroll
    for (int j = 0; j < 4; j++) {
        int oc = ocBase + ocg + 16 * j;
        float inv = 1.f / g_sigma[(1 * NB + n) * C + oc];
        float bias = c_b[oc];
#pragma unroll
        for (int xx = 0; xx < 8; xx++) {
            int xq = x0 + xg * 8 + xx;
            float vv = acc[j][xx] * inv + bias;
            vv += ns * noise2[n * PIX + y * HO + xq];
            vv = vv > 0.f ? vv : 0.2f * vv;
            out[((size_t)(n * C + oc) * HO + y) * HO + xq] = vv;
        }
    }
}

// ---------------------------------------------------------------------------
// K5: toRGB (1x1 modulated conv, no demod) + lrelu + bilinear 2x skip add
// ---------------------------------------------------------------------------
__device__ __forceinline__ void bl_coords(int Y, int& k0, int& k1, float& w0, float& w1) {
    if (Y & 1) { k0 = (Y - 1) >> 1; k1 = k0 + 1 < 31 ? k0 + 1 : 31; w0 = 0.75f; w1 = 0.25f; }
    else       { int k = Y >> 1; k0 = k - 1 > 0 ? k - 1 : 0; k1 = k; w0 = 0.25f; w1 = 0.75f; }
}

__global__ void k_rgb(const float* __restrict__ yimg, const float* __restrict__ rgb_w,
                      const float* __restrict__ rgb_b, float* __restrict__ out) {
    __shared__ float sw3[3][C];
    const int n = blockIdx.y;
    const int tid = threadIdx.x;
    for (int e = tid; e < 3 * C; e += 256) {
        int c = e >> 9, ci = e & 511;
        sw3[c][ci] = rgb_w[c * C + ci] * g_s[(2 * NB + n) * C + ci];
    }
    __syncthreads();

    const int px = blockIdx.x * 1024 + tid * 4;   // 4 consecutive pixels
    const float* h2 = out + (size_t)n * C * PIX;
    float a0x = 0, a0y = 0, a0z = 0, a0w = 0;
    float a1x = 0, a1y = 0, a1z = 0, a1w = 0;
    float a2x = 0, a2y = 0, a2z = 0, a2w = 0;
#pragma unroll 4
    for (int ci = 0; ci < C; ci++) {
        float4 hv = *(const float4*)(h2 + (size_t)ci * PIX + px);
        float w0 = sw3[0][ci], w1 = sw3[1][ci], w2 = sw3[2][ci];
        a0x = fmaf(hv.x, w0, a0x); a0y = fmaf(hv.y, w0, a0y);
        a0z = fmaf(hv.z, w0, a0z); a0w = fmaf(hv.w, w0, a0w);
        a1x = fmaf(hv.x, w1, a1x); a1y = fmaf(hv.y, w1, a1y);
        a1z = fmaf(hv.z, w1, a1z); a1w = fmaf(hv.w, w1, a1w);
        a2x = fmaf(hv.x, w2, a2x); a2y = fmaf(hv.y, w2, a2y);
        a2z = fmaf(hv.z, w2, a2z); a2w = fmaf(hv.w, w2, a2w);
    }

    float accv[3][4] = {{a0x, a0y, a0z, a0w}, {a1x, a1y, a1z, a1w}, {a2x, a2y, a2z, a2w}};
    const int Y = px >> 6;
    const int X0 = px & 63;
    int ky0, ky1; float wy0, wy1;
    bl_coords(Y, ky0, ky1, wy0, wy1);
    const size_t IMG_OFF = (size_t)NB * C * PIX;

#pragma unroll
    for (int c = 0; c < 3; c++) {
        float bias = rgb_b[c];
        const float* yb = yimg + (size_t)(n * 3 + c) * HI * HI;
#pragma unroll
        for (int k = 0; k < 4; k++) {
            float r = accv[c][k] + bias;
            r = r > 0.f ? r : 0.2f * r;
            int X = X0 + k;
            int kx0, kx1; float wx0, wx1;
            bl_coords(X, kx0, kx1, wx0, wx1);
            float bv = wy0 * (wx0 * yb[ky0 * HI + kx0] + wx1 * yb[ky0 * HI + kx1])
                     + wy1 * (wx0 * yb[ky1 * HI + kx0] + wx1 * yb[ky1 * HI + kx1]);
            out[IMG_OFF + (size_t)(n * 3 + c) * PIX + px + k] = bv + r;
        }
    }
}

// ---------------------------------------------------------------------------
extern "C" void kernel_launch(void* const* d_in, const int* in_sizes, int n_in,
                              void* d_out, int out_size) {
    const float* x       = (const float*)d_in[0];
    const float* v       = (const float*)d_in[1];
    const float* yimg    = (const float*)d_in[2];
    const float* noise1  = (const float*)d_in[3];
    const float* noise2  = (const float*)d_in[4];
    const float* up_w    = (const float*)d_in[5];
    const float* up_b    = (const float*)d_in[6];
    const float* up_sw   = (const float*)d_in[7];
    const float* up_sb   = (const float*)d_in[8];
    const float* c_w     = (const float*)d_in[9];
    const float* c_b     = (const float*)d_in[10];
    const float* c_sw    = (const float*)d_in[11];
    const float* c_sb    = (const float*)d_in[12];
    const float* rgb_w   = (const float*)d_in[13];
    const float* rgb_b   = (const float*)d_in[14];
    const float* rgb_sw  = (const float*)d_in[15];
    const float* rgb_sb  = (const float*)d_in[16];
    const float* nsp     = (const float*)d_in[17];
    float* out = (float*)d_out;

    k_wsq<<<2048, 256>>>(up_w, c_w);
    k_style<<<dim3(NB, 3), C>>>(v, up_sw, up_sb, c_sw, c_sb, rgb_sw, rgb_sb);
    k_sigma<<<dim3(NB, 2), C>>>();
    k_upconv<<<dim3(32, 8, NB), 256>>>(x, up_w, up_b, noise1, nsp);
    k_conv3<<<dim3(32, 8, NB), 256>>>(c_w, c_b, noise2, nsp, out);
    k_rgb<<<dim3(4, NB), 256>>>(yimg, rgb_w, rgb_b, out);
}

// round 7
// speedup vs baseline: 1.7898x; 1.7898x over previous
#include <cuda_runtime.h>
#include <cstdint>
#include <math.h>

#define NB 8
#define C 512
#define HO 64
#define PIX 4096
#define KTOT 4608
#define NT 144            // K tiles of 32

// ---------------- device scratch ------------------------------------------
// channels-last padded activations [n][66][66][512], per-8 channel perm {0,4,1,5,2,6,3,7}
__device__ __align__(128) float g_xzp[(size_t)NB * 66 * 66 * 512];
__device__ __align__(128) float g_h1p[(size_t)NB * 66 * 66 * 512];
// fragment-layout weights: [mtile4][ktile144][part2][mf8][ks4][lane32][e4]
__device__ __align__(128) float g_Ac2[(size_t)4 * 144 * 8192];
__device__ __align__(128) float g_Au2[(size_t)4 * 144 * 8192];
__device__ float g_wsq_up[C * C];
__device__ float g_wsq_cT[C * C];
__device__ float g_s[3 * NB * C];
__device__ float g_sigma[2 * NB * C];

// ---------------- helpers --------------------------------------------------
__device__ __forceinline__ uint32_t smem_u32(const void* p) {
    uint32_t a;
    asm("{ .reg .u64 t; cvta.to.shared.u64 t, %1; cvt.u32.u64 %0, t; }" : "=r"(a) : "l"(p));
    return a;
}
__device__ __forceinline__ float tf32r(float x) {
    uint32_t u;
    asm("cvt.rn.tf32.f32 %0, %1;" : "=r"(u) : "f"(x));
    return __uint_as_float(u);
}
__device__ __forceinline__ void cpa16(uint32_t s, const void* g) {
    asm volatile("cp.async.cg.shared.global [%0], [%1], 16;" :: "r"(s), "l"(g));
}
__device__ __forceinline__ void mma8(float* c, uint4 a, uint2 b) {
    asm volatile("mma.sync.aligned.m16n8k8.row.col.f32.tf32.tf32.f32 "
        "{%0,%1,%2,%3},{%4,%5,%6,%7},{%8,%9},{%0,%1,%2,%3};"
        : "+f"(c[0]), "+f"(c[1]), "+f"(c[2]), "+f"(c[3])
        : "r"(a.x), "r"(a.y), "r"(a.z), "r"(a.w), "r"(b.x), "r"(b.y));
}

// ---------------------------------------------------------------------------
// K0: weight-square tap sums (fp32 exact, for demod sigma)
// ---------------------------------------------------------------------------
__global__ void k_wsq(const float* __restrict__ up_w, const float* __restrict__ c_w) {
    int idx = blockIdx.x * blockDim.x + threadIdx.x;
    int which = idx >> 18;
    int p = idx & 262143;
    int i = p >> 9, o = p & 511;
    const float* src = which == 0 ? (up_w + ((i << 9) + o) * 9)
                                  : (c_w + ((o << 9) + i) * 9);
    float s = 0.f;
#pragma unroll
    for (int t = 0; t < 9; t++) s += src[t] * src[t];
    if (which == 0) g_wsq_up[p] = s;
    else            g_wsq_cT[p] = s;
}

// ---------------------------------------------------------------------------
// K1: style vectors s = v @ SW + SB
// ---------------------------------------------------------------------------
__global__ void k_style(const float* __restrict__ v,
                        const float* __restrict__ up_sw, const float* __restrict__ up_sb,
                        const float* __restrict__ c_sw,  const float* __restrict__ c_sb,
                        const float* __restrict__ rgb_sw,const float* __restrict__ rgb_sb) {
    int m = blockIdx.y, n = blockIdx.x, i = threadIdx.x;
    __shared__ float sv[C];
    sv[i] = v[n * C + i];
    __syncthreads();
    const float* SW = (m == 0) ? up_sw : (m == 1) ? c_sw : rgb_sw;
    const float* SB = (m == 0) ? up_sb : (m == 1) ? c_sb : rgb_sb;
    float acc = SB[i];
#pragma unroll 4
    for (int l = 0; l < C; l++) acc = fmaf(sv[l], SW[l * C + i], acc);
    g_s[(m * NB + n) * C + i] = acc;
}

// ---------------------------------------------------------------------------
// K2: demod sigma
// ---------------------------------------------------------------------------
__global__ void k_sigma(void) {
    int m = blockIdx.y, n = blockIdx.x, o = threadIdx.x;
    __shared__ float s2[C];
    float sv = g_s[(m * NB + n) * C + o];
    s2[o] = sv * sv;
    __syncthreads();
    const float* wsq = (m == 0) ? g_wsq_up : g_wsq_cT;
    float acc = 1e-8f;
#pragma unroll 4
    for (int i = 0; i < C; i++) acc = fmaf(s2[i], wsq[i * C + o], acc);
    g_sigma[(m * NB + n) * C + o] = sqrtf(acc);
}

// ---------------------------------------------------------------------------
// K3: dilated+padded+modulated x -> g_xzp channels-last (perm within 8-group)
//   logical: D[n][1+2a][1+2b][ci] = tf32(x[n][ci][a][b] * s_up), else 0
//   storage pos j in 8-group holds channel o8[j], o8={0,4,1,5,2,6,3,7}
// ---------------------------------------------------------------------------
__global__ void k_dilate(const float* __restrict__ x) {
    size_t idx = (size_t)blockIdx.x * 256 + threadIdx.x;   // float4 over 8*66*66*128
    if (idx >= (size_t)NB * 66 * 66 * 128) return;
    int ci4 = (int)(idx & 127);
    int cell = (int)(idx >> 7);
    int xz = cell % 66; int t2 = cell / 66; int yz = t2 % 66; int nn = t2 / 66;
    float4 v = make_float4(0.f, 0.f, 0.f, 0.f);
    if ((yz & 1) && (xz & 1)) {
        int a = yz >> 1, b = xz >> 1;
        if (a < 32 && b < 32) {
            int g = (ci4 >> 1) * 8;
            int hi = ci4 & 1;
            int c0 = g + (hi ? 2 : 0), c1 = g + (hi ? 6 : 4);
            int c2 = g + (hi ? 3 : 1), c3 = g + (hi ? 7 : 5);
            const float* sp = g_s + (0 * NB + nn) * C;
            const float* xp = x + (((size_t)nn * 512) * 32 + a) * 32 + b;
            v.x = tf32r(xp[(size_t)c0 * 1024] * sp[c0]);
            v.y = tf32r(xp[(size_t)c1 * 1024] * sp[c1]);
            v.z = tf32r(xp[(size_t)c2 * 1024] * sp[c2]);
            v.w = tf32r(xp[(size_t)c3 * 1024] * sp[c3]);
        }
    }
    ((float4*)g_xzp)[idx] = v;
}

// ---------------------------------------------------------------------------
// K3b: zero the halo of g_h1p
// ---------------------------------------------------------------------------
__global__ void k_halo(void) {
    int idx = blockIdx.x * 256 + threadIdx.x;   // 8*260*128
    if (idx >= NB * 260 * 128) return;
    int ci4 = idx & 127;
    int c2 = idx >> 7;
    int h = c2 % 260, nn = c2 / 260;
    int yz, xz;
    if (h < 66)       { yz = 0;  xz = h; }
    else if (h < 132) { yz = 65; xz = h - 66; }
    else { int rem = h - 132; yz = 1 + (rem >> 1); xz = (rem & 1) * 65; }
    ((float4*)g_h1p)[((size_t)(nn * 66 + yz) * 66 + xz) * 128 + ci4] =
        make_float4(0.f, 0.f, 0.f, 0.f);
}

// ---------------------------------------------------------------------------
// K3c: weights -> fragment-layout hi/lo tf32 split.
//   flat off = ((((mtile*144+kt)*2+part)*8+mf)*4+ks)*128 + lane*4 + e
//   element: m = mf*16 + (lane>>2) + (e&1)*8 ; kk = ks*8 + (lane&3) + (e>>1)*4
//   conv3 : w = c_w[oc][ci][t] ; upconv: w = up_w[ci][oc][8-t]   (t = k/512)
//   Each matrix has 4*144*8192 = 4718592 elements (hi+lo).
// ---------------------------------------------------------------------------
#define AFRAG_ELEMS 4718592
__global__ void k_prepA2(const float* __restrict__ up_w, const float* __restrict__ c_w) {
    int idx = blockIdx.x * 256 + threadIdx.x;   // 0 .. 2*4718592
    int which = idx >= AFRAG_ELEMS;
    int off = which ? idx - AFRAG_ELEMS : idx;
    int e = off & 3, lane = (off >> 2) & 31, ks = (off >> 7) & 3;
    int mf = (off >> 9) & 7, part = (off >> 12) & 1;
    int rest = off >> 13;
    int kt = rest % 144, mtile = rest / 144;
    int grp = lane >> 2, tig = lane & 3;
    int m = mf * 16 + grp + (e & 1) * 8;
    int kk = ks * 8 + tig + (e >> 1) * 4;
    int oc = mtile * 128 + m;
    int kg = kt * 32 + kk;
    int t = kg >> 9, ci = kg & 511;
    float w = which ? up_w[((size_t)ci * 512 + oc) * 9 + (8 - t)]
                    : c_w[((size_t)oc * 512 + ci) * 9 + t];
    float hi = tf32r(w);
    float val = part == 0 ? hi : tf32r(w - hi);
    if (which) g_Au2[off] = val;
    else       g_Ac2[off] = val;
}

// ---------------------------------------------------------------------------
// K4: tf32 mma.sync implicit-GEMM conv. CTA: M=128 oc x N=256 px, K=4608.
// 8 warps (2 Mx4 N) of 64x64. Weights hi/lo (2 MMA passes). cp.async 2-stage.
// MODE 0 (upconv): In=g_xzp, A=g_Au2; epi -> g_h1p (modulated, tf32, perm CL)
// MODE 1 (conv3):  In=g_h1p, A=g_Ac2; epi -> d_out h (NCHW)
// ---------------------------------------------------------------------------
template <int MODE>
__global__ void __launch_bounds__(256)
k_gemm(const float* __restrict__ bias_, const float* __restrict__ noise,
       const float* __restrict__ nsp, float* __restrict__ outp) {
    extern __shared__ char sm[];
    const int tid = threadIdx.x;
    const int wid = tid >> 5, lane = tid & 31;
    const int warpM = wid >> 2, warpN = wid & 3;
    const int grp = lane >> 2, tig = lane & 3;

    const int mtile = blockIdx.x;            // 0..3
    const int ocb = mtile << 7;
    const int n_img = blockIdx.y >> 4;
    const int blk = blockIdx.y & 15;
    const int pix0 = blk << 8;
    const int y0 = pix0 >> 6;

    const float* In = MODE ? g_h1p : g_xzp;
    const char* Ablock = (const char*)(MODE ? g_Ac2 : g_Au2) + (size_t)mtile * 144 * 32768;
    const char* Bimg = (const char*)In + (size_t)n_img * (66 * 66 * 512) * 4;
    const uint32_t sb = smem_u32(sm);

    // per-thread B copy offsets (8 x 16B units)
    uint32_t pixoff[8], soff[8];
#pragma unroll
    for (int it = 0; it < 8; it++) {
        int c = tid + 256 * it;
        int nn = c >> 3, r = c & 7;
        int py = y0 + (nn >> 6), px = nn & 63;
        pixoff[it] = (uint32_t)(py * 66 + px) * 2048u + (uint32_t)r * 16u;
        soff[it] = (uint32_t)((r >> 1) * 8192 + nn * 32 + (r & 1) * 16);
    }

    float acc[4][8][4];
#pragma unroll
    for (int a = 0; a < 4; a++)
#pragma unroll
        for (int b = 0; b < 8; b++)
#pragma unroll
            for (int e = 0; e < 4; e++) acc[a][b][e] = 0.f;

    // tile loader
    auto load_tile = [&](int kt, int s) {
        uint32_t sa = sb + (uint32_t)s * 65536u;
        const char* ag = Ablock + (size_t)kt * 32768;
#pragma unroll
        for (int it = 0; it < 8; it++)
            cpa16(sa + (uint32_t)(tid * 16 + it * 4096), ag + tid * 16 + it * 4096);
        int t = kt >> 4, chunk = kt & 15;
        int dy = t / 3, dx = t - dy * 3;
        const char* bg = Bimg + (dy * 66 + dx) * 2048 + chunk * 128;
        uint32_t sbB = sa + 32768u;
#pragma unroll
        for (int it = 0; it < 8; it++)
            cpa16(sbB + soff[it], bg + pixoff[it]);
        asm volatile("cp.async.commit_group;" ::: "memory");
    };

    load_tile(0, 0);
    load_tile(1, 1);

#pragma unroll 1
    for (int kt = 0; kt < NT; kt++) {
        if (kt < NT - 1) asm volatile("cp.async.wait_group 1;" ::: "memory");
        else             asm volatile("cp.async.wait_group 0;" ::: "memory");
        __syncthreads();

        const char* stg = sm + (kt & 1) * 65536;
        const char* aW = stg + ((warpM * 4) * 4) * 512;
        const char* bW = stg + 32768 + (warpN * 64 + grp) * 32 + tig * 8;

#pragma unroll
        for (int ks = 0; ks < 4; ks++) {
            uint2 bf[8];
#pragma unroll
            for (int nf = 0; nf < 8; nf++)
                bf[nf] = *(const uint2*)(bW + ks * 8192 + nf * 256);
            uint4 af[4];
#pragma unroll
            for (int mf = 0; mf < 4; mf++)
                af[mf] = *(const uint4*)(aW + (mf * 4 + ks) * 512 + lane * 16);
#pragma unroll
            for (int mf = 0; mf < 4; mf++)
#pragma unroll
                for (int nf = 0; nf < 8; nf++)
                    mma8(acc[mf][nf], af[mf], bf[nf]);
#pragma unroll
            for (int mf = 0; mf < 4; mf++)
                af[mf] = *(const uint4*)(aW + 16384 + (mf * 4 + ks) * 512 + lane * 16);
#pragma unroll
            for (int mf = 0; mf < 4; mf++)
#pragma unroll
                for (int nf = 0; nf < 8; nf++)
                    mma8(acc[mf][nf], af[mf], bf[nf]);
        }
        __syncthreads();
        if (kt + 2 < NT) load_tile(kt + 2, kt & 1);
    }

    // ---------------- epilogue ----------------
    const float ns = nsp[0];
#pragma unroll
    for (int mf = 0; mf < 4; mf++) {
#pragma unroll
        for (int h2 = 0; h2 < 2; h2++) {
            int oc = ocb + warpM * 64 + mf * 16 + grp + h2 * 8;
            float inv = 1.f / g_sigma[(MODE * NB + n_img) * C + oc];
            float bias = bias_[oc];
            float sc = (MODE == 0) ? g_s[(1 * NB + n_img) * C + oc] : 0.f;
            int ocpos = (oc & ~7) | ((oc & 3) * 2 + ((oc >> 2) & 1));
#pragma unroll
            for (int nf = 0; nf < 8; nf++) {
                int pix = pix0 + warpN * 64 + nf * 8 + 2 * tig;
                float2 nz = *(const float2*)(noise + (size_t)n_img * PIX + pix);
                float v0 = acc[mf][nf][h2 * 2 + 0] * inv + bias + ns * nz.x;
                float v1 = acc[mf][nf][h2 * 2 + 1] * inv + bias + ns * nz.y;
                v0 = v0 > 0.f ? v0 : 0.2f * v0;
                v1 = v1 > 0.f ? v1 : 0.2f * v1;
                if (MODE == 0) {
                    int py = pix >> 6, px = pix & 63;
                    float* hb = g_h1p + (size_t)n_img * (66 * 66 * 512);
                    hb[((size_t)(py + 1) * 66 + (px + 1)) * 512 + ocpos] = tf32r(v0 * sc);
                    hb[((size_t)(py + 1) * 66 + (px + 2)) * 512 + ocpos] = tf32r(v1 * sc);
                } else {
                    *(float2*)(outp + ((size_t)(n_img * 512 + oc) * PIX) + pix) =
                        make_float2(v0, v1);
                }
            }
        }
    }
}

// ---------------------------------------------------------------------------
// K5: toRGB (1x1 modulated conv, no demod) + lrelu + bilinear 2x skip add
// ---------------------------------------------------------------------------
__device__ __forceinline__ void bl_coords(int Y, int& k0, int& k1, float& w0, float& w1) {
    if (Y & 1) { k0 = (Y - 1) >> 1; k1 = k0 + 1 < 31 ? k0 + 1 : 31; w0 = 0.75f; w1 = 0.25f; }
    else       { int k = Y >> 1; k0 = k - 1 > 0 ? k - 1 : 0; k1 = k; w0 = 0.25f; w1 = 0.75f; }
}

__global__ void k_rgb(const float* __restrict__ yimg, const float* __restrict__ rgb_w,
                      const float* __restrict__ rgb_b, float* __restrict__ out) {
    __shared__ float sw3[3][C];
    const int n = blockIdx.y;
    const int tid = threadIdx.x;
    for (int e = tid; e < 3 * C; e += 256) {
        int c = e >> 9, ci = e & 511;
        sw3[c][ci] = rgb_w[c * C + ci] * g_s[(2 * NB + n) * C + ci];
    }
    __syncthreads();

    const int px = blockIdx.x * 1024 + tid * 4;
    const float* h2 = out + (size_t)n * C * PIX;
    float a0x = 0, a0y = 0, a0z = 0, a0w = 0;
    float a1x = 0, a1y = 0, a1z = 0, a1w = 0;
    float a2x = 0, a2y = 0, a2z = 0, a2w = 0;
#pragma unroll 4
    for (int ci = 0; ci < C; ci++) {
        float4 hv = *(const float4*)(h2 + (size_t)ci * PIX + px);
        float w0 = sw3[0][ci], w1 = sw3[1][ci], w2 = sw3[2][ci];
        a0x = fmaf(hv.x, w0, a0x); a0y = fmaf(hv.y, w0, a0y);
        a0z = fmaf(hv.z, w0, a0z); a0w = fmaf(hv.w, w0, a0w);
        a1x = fmaf(hv.x, w1, a1x); a1y = fmaf(hv.y, w1, a1y);
        a1z = fmaf(hv.z, w1, a1z); a1w = fmaf(hv.w, w1, a1w);
        a2x = fmaf(hv.x, w2, a2x); a2y = fmaf(hv.y, w2, a2y);
        a2z = fmaf(hv.z, w2, a2z); a2w = fmaf(hv.w, w2, a2w);
    }

    float accv[3][4] = {{a0x, a0y, a0z, a0w}, {a1x, a1y, a1z, a1w}, {a2x, a2y, a2z, a2w}};
    const int Y = px >> 6;
    const int X0 = px & 63;
    int ky0, ky1; float wy0, wy1;
    bl_coords(Y, ky0, ky1, wy0, wy1);
    const size_t IMG_OFF = (size_t)NB * C * PIX;

#pragma unroll
    for (int c = 0; c < 3; c++) {
        float bias = rgb_b[c];
        const float* yb = yimg + (size_t)(n * 3 + c) * 32 * 32;
#pragma unroll
        for (int k = 0; k < 4; k++) {
            float r = accv[c][k] + bias;
            r = r > 0.f ? r : 0.2f * r;
            int X = X0 + k;
            int kx0, kx1; float wx0, wx1;
            bl_coords(X, kx0, kx1, wx0, wx1);
            float bv = wy0 * (wx0 * yb[ky0 * 32 + kx0] + wx1 * yb[ky0 * 32 + kx1])
                     + wy1 * (wx0 * yb[ky1 * 32 + kx0] + wx1 * yb[ky1 * 32 + kx1]);
            out[IMG_OFF + (size_t)(n * 3 + c) * PIX + px + k] = bv + r;
        }
    }
}

// ---------------------------------------------------------------------------
extern "C" void kernel_launch(void* const* d_in, const int* in_sizes, int n_in,
                              void* d_out, int out_size) {
    const float* x       = (const float*)d_in[0];
    const float* v       = (const float*)d_in[1];
    const float* yimg    = (const float*)d_in[2];
    const float* noise1  = (const float*)d_in[3];
    const float* noise2  = (const float*)d_in[4];
    const float* up_w    = (const float*)d_in[5];
    const float* up_b    = (const float*)d_in[6];
    const float* up_sw   = (const float*)d_in[7];
    const float* up_sb   = (const float*)d_in[8];
    const float* c_w     = (const float*)d_in[9];
    const float* c_b     = (const float*)d_in[10];
    const float* c_sw    = (const float*)d_in[11];
    const float* c_sb    = (const float*)d_in[12];
    const float* rgb_w   = (const float*)d_in[13];
    const float* rgb_b   = (const float*)d_in[14];
    const float* rgb_sw  = (const float*)d_in[15];
    const float* rgb_sb  = (const float*)d_in[16];
    const float* nsp     = (const float*)d_in[17];
    float* out = (float*)d_out;

    const int SMEM_GEMM = 131072;
    cudaFuncSetAttribute(k_gemm<0>, cudaFuncAttributeMaxDynamicSharedMemorySize, SMEM_GEMM);
    cudaFuncSetAttribute(k_gemm<1>, cudaFuncAttributeMaxDynamicSharedMemorySize, SMEM_GEMM);

    k_style<<<dim3(NB, 3), C>>>(v, up_sw, up_sb, c_sw, c_sb, rgb_sw, rgb_sb);
    k_wsq<<<2048, 256>>>(up_w, c_w);
    k_sigma<<<dim3(NB, 2), C>>>();
    k_dilate<<<17424, 256>>>(x);
    k_prepA2<<<36864, 256>>>(up_w, c_w);   // FIXED: full hi+lo coverage (2 x 4718592)
    k_halo<<<1040, 256>>>();
    k_gemm<0><<<dim3(4, 128), 256, SMEM_GEMM>>>(up_b, noise1, nsp, out);
    k_gemm<1><<<dim3(4, 128), 256, SMEM_GEMM>>>(c_b, noise2, nsp, out);
    k_rgb<<<dim3(4, NB), 256>>>(yimg, rgb_w, rgb_b, out);
}

// round 8
// speedup vs baseline: 3.0488x; 1.7034x over previous
#include <cuda_runtime.h>
#include <cstdint>
#include <math.h>

#define NB 8
#define C 512
#define HO 64
#define PIX 4096
#define KTOT 4608
#define NT 144            // K tiles of 32

// ---------------- device scratch ------------------------------------------
// channels-last padded activations [n][66][66][512], per-8 channel perm {0,4,1,5,2,6,3,7}
__device__ __align__(128) float g_xzp[(size_t)NB * 66 * 66 * 512];
__device__ __align__(128) float g_h1p[(size_t)NB * 66 * 66 * 512];
// fragment-layout weights: [mtile4][ktile144][mf8][ks4][lane32][e4]  (single tf32)
__device__ __align__(128) float g_Ac2[(size_t)4 * 144 * 4096];
__device__ __align__(128) float g_Au2[(size_t)4 * 144 * 4096];
__device__ float g_wsq_up[C * C];
__device__ float g_wsq_cT[C * C];
__device__ float g_s[3 * NB * C];
__device__ float g_sigma[2 * NB * C];

// ---------------- helpers --------------------------------------------------
__device__ __forceinline__ uint32_t smem_u32(const void* p) {
    uint32_t a;
    asm("{ .reg .u64 t; cvta.to.shared.u64 t, %1; cvt.u32.u64 %0, t; }" : "=r"(a) : "l"(p));
    return a;
}
__device__ __forceinline__ float tf32r(float x) {
    uint32_t u;
    asm("cvt.rn.tf32.f32 %0, %1;" : "=r"(u) : "f"(x));
    return __uint_as_float(u);
}
__device__ __forceinline__ void cpa16(uint32_t s, const void* g) {
    asm volatile("cp.async.cg.shared.global [%0], [%1], 16;" :: "r"(s), "l"(g));
}
__device__ __forceinline__ void mma8(float* c, uint4 a, uint2 b) {
    asm volatile("mma.sync.aligned.m16n8k8.row.col.f32.tf32.tf32.f32 "
        "{%0,%1,%2,%3},{%4,%5,%6,%7},{%8,%9},{%0,%1,%2,%3};"
        : "+f"(c[0]), "+f"(c[1]), "+f"(c[2]), "+f"(c[3])
        : "r"(a.x), "r"(a.y), "r"(a.z), "r"(a.w), "r"(b.x), "r"(b.y));
}

// ---------------------------------------------------------------------------
// K0: weight-square tap sums (fp32 exact, for demod sigma)
// ---------------------------------------------------------------------------
__global__ void k_wsq(const float* __restrict__ up_w, const float* __restrict__ c_w) {
    int idx = blockIdx.x * blockDim.x + threadIdx.x;
    int which = idx >> 18;
    int p = idx & 262143;
    int i = p >> 9, o = p & 511;
    const float* src = which == 0 ? (up_w + ((i << 9) + o) * 9)
                                  : (c_w + ((o << 9) + i) * 9);
    float s = 0.f;
#pragma unroll
    for (int t = 0; t < 9; t++) s += src[t] * src[t];
    if (which == 0) g_wsq_up[p] = s;
    else            g_wsq_cT[p] = s;
}

// ---------------------------------------------------------------------------
// K1: style vectors s = v @ SW + SB
// ---------------------------------------------------------------------------
__global__ void k_style(const float* __restrict__ v,
                        const float* __restrict__ up_sw, const float* __restrict__ up_sb,
                        const float* __restrict__ c_sw,  const float* __restrict__ c_sb,
                        const float* __restrict__ rgb_sw,const float* __restrict__ rgb_sb) {
    int m = blockIdx.y, n = blockIdx.x, i = threadIdx.x;
    __shared__ float sv[C];
    sv[i] = v[n * C + i];
    __syncthreads();
    const float* SW = (m == 0) ? up_sw : (m == 1) ? c_sw : rgb_sw;
    const float* SB = (m == 0) ? up_sb : (m == 1) ? c_sb : rgb_sb;
    float acc = SB[i];
#pragma unroll 4
    for (int l = 0; l < C; l++) acc = fmaf(sv[l], SW[l * C + i], acc);
    g_s[(m * NB + n) * C + i] = acc;
}

// ---------------------------------------------------------------------------
// K2: demod sigma
// ---------------------------------------------------------------------------
__global__ void k_sigma(void) {
    int m = blockIdx.y, n = blockIdx.x, o = threadIdx.x;
    __shared__ float s2[C];
    float sv = g_s[(m * NB + n) * C + o];
    s2[o] = sv * sv;
    __syncthreads();
    const float* wsq = (m == 0) ? g_wsq_up : g_wsq_cT;
    float acc = 1e-8f;
#pragma unroll 4
    for (int i = 0; i < C; i++) acc = fmaf(s2[i], wsq[i * C + o], acc);
    g_sigma[(m * NB + n) * C + o] = sqrtf(acc);
}

// ---------------------------------------------------------------------------
// K3: dilated+padded+modulated x -> g_xzp channels-last (perm within 8-group)
// ---------------------------------------------------------------------------
__global__ void k_dilate(const float* __restrict__ x) {
    size_t idx = (size_t)blockIdx.x * 256 + threadIdx.x;   // float4 over 8*66*66*128
    if (idx >= (size_t)NB * 66 * 66 * 128) return;
    int ci4 = (int)(idx & 127);
    int cell = (int)(idx >> 7);
    int xz = cell % 66; int t2 = cell / 66; int yz = t2 % 66; int nn = t2 / 66;
    float4 v = make_float4(0.f, 0.f, 0.f, 0.f);
    if ((yz & 1) && (xz & 1)) {
        int a = yz >> 1, b = xz >> 1;
        if (a < 32 && b < 32) {
            int g = (ci4 >> 1) * 8;
            int hi = ci4 & 1;
            int c0 = g + (hi ? 2 : 0), c1 = g + (hi ? 6 : 4);
            int c2 = g + (hi ? 3 : 1), c3 = g + (hi ? 7 : 5);
            const float* sp = g_s + (0 * NB + nn) * C;
            const float* xp = x + (((size_t)nn * 512) * 32 + a) * 32 + b;
            v.x = tf32r(xp[(size_t)c0 * 1024] * sp[c0]);
            v.y = tf32r(xp[(size_t)c1 * 1024] * sp[c1]);
            v.z = tf32r(xp[(size_t)c2 * 1024] * sp[c2]);
            v.w = tf32r(xp[(size_t)c3 * 1024] * sp[c3]);
        }
    }
    ((float4*)g_xzp)[idx] = v;
}

// ---------------------------------------------------------------------------
// K3b: zero the halo of g_h1p
// ---------------------------------------------------------------------------
__global__ void k_halo(void) {
    int idx = blockIdx.x * 256 + threadIdx.x;   // 8*260*128
    if (idx >= NB * 260 * 128) return;
    int ci4 = idx & 127;
    int c2 = idx >> 7;
    int h = c2 % 260, nn = c2 / 260;
    int yz, xz;
    if (h < 66)       { yz = 0;  xz = h; }
    else if (h < 132) { yz = 65; xz = h - 66; }
    else { int rem = h - 132; yz = 1 + (rem >> 1); xz = (rem & 1) * 65; }
    ((float4*)g_h1p)[((size_t)(nn * 66 + yz) * 66 + xz) * 128 + ci4] =
        make_float4(0.f, 0.f, 0.f, 0.f);
}

// ---------------------------------------------------------------------------
// K3c: weights -> fragment layout, single tf32 (RN).
//   flat off = (((mtile*144+kt)*8+mf)*4+ks)*128 + lane*4 + e
//   element: m = mf*16 + (lane>>2) + (e&1)*8 ; kk = ks*8 + (lane&3) + (e>>1)*4
//   conv3 : w = c_w[oc][ci][t] ; upconv: w = up_w[ci][oc][8-t]   (t = k/512)
//   Each matrix: 4*144*4096 = 2359296 elements.
// ---------------------------------------------------------------------------
#define AFRAG_ELEMS 2359296
__global__ void k_prepA2(const float* __restrict__ up_w, const float* __restrict__ c_w) {
    int idx = blockIdx.x * 256 + threadIdx.x;   // 0 .. 2*2359296
    int which = idx >= AFRAG_ELEMS;
    int off = which ? idx - AFRAG_ELEMS : idx;
    int e = off & 3, lane = (off >> 2) & 31, ks = (off >> 7) & 3;
    int mf = (off >> 9) & 7;
    int rest = off >> 12;
    int kt = rest % 144, mtile = rest / 144;
    int grp = lane >> 2, tig = lane & 3;
    int m = mf * 16 + grp + (e & 1) * 8;
    int kk = ks * 8 + tig + (e >> 1) * 4;
    int oc = mtile * 128 + m;
    int kg = kt * 32 + kk;
    int t = kg >> 9, ci = kg & 511;
    float w = which ? up_w[((size_t)ci * 512 + oc) * 9 + (8 - t)]
                    : c_w[((size_t)oc * 512 + ci) * 9 + t];
    float val = tf32r(w);
    if (which) g_Au2[off] = val;
    else       g_Ac2[off] = val;
}

// ---------------------------------------------------------------------------
// K4: tf32 mma.sync implicit-GEMM conv. CTA: M=128 oc x N=256 px, K=4608.
// 8 warps (2 Mx4 N) of 64x64. Single tf32 pass. 4-stage cp.async pipeline,
// ONE __syncthreads per K-iteration (stage kt+3 never aliases stage kt).
// MODE 0 (upconv): In=g_xzp, A=g_Au2; epi -> g_h1p (modulated, tf32, perm CL)
// MODE 1 (conv3):  In=g_h1p, A=g_Ac2; epi -> d_out h (NCHW)
// ---------------------------------------------------------------------------
#define STAGE_BYTES 49152   // 16KB A + 32KB B
template <int MODE>
__global__ void __launch_bounds__(256)
k_gemm(const float* __restrict__ bias_, const float* __restrict__ noise,
       const float* __restrict__ nsp, float* __restrict__ outp) {
    extern __shared__ char sm[];
    const int tid = threadIdx.x;
    const int wid = tid >> 5, lane = tid & 31;
    const int warpM = wid >> 2, warpN = wid & 3;
    const int grp = lane >> 2, tig = lane & 3;

    const int mtile = blockIdx.x;            // 0..3
    const int ocb = mtile << 7;
    const int n_img = blockIdx.y >> 4;
    const int blk = blockIdx.y & 15;
    const int pix0 = blk << 8;
    const int y0 = pix0 >> 6;

    const float* In = MODE ? g_h1p : g_xzp;
    const char* Ablock = (const char*)(MODE ? g_Ac2 : g_Au2) + (size_t)mtile * 144 * 16384;
    const char* Bimg = (const char*)In + (size_t)n_img * (66 * 66 * 512) * 4;
    const uint32_t sb = smem_u32(sm);

    // per-thread B copy offsets (8 x 16B units)
    uint32_t pixoff[8], soff[8];
#pragma unroll
    for (int it = 0; it < 8; it++) {
        int c = tid + 256 * it;
        int nn = c >> 3, r = c & 7;
        int py = y0 + (nn >> 6), px = nn & 63;
        pixoff[it] = (uint32_t)(py * 66 + px) * 2048u + (uint32_t)r * 16u;
        soff[it] = (uint32_t)((r >> 1) * 8192 + nn * 32 + (r & 1) * 16);
    }

    float acc[4][8][4];
#pragma unroll
    for (int a = 0; a < 4; a++)
#pragma unroll
        for (int b = 0; b < 8; b++)
#pragma unroll
            for (int e = 0; e < 4; e++) acc[a][b][e] = 0.f;

    // tile loader: A (16KB) + B (32KB) into stage s
    auto load_tile = [&](int kt, int s) {
        uint32_t sa = sb + (uint32_t)s * STAGE_BYTES;
        const char* ag = Ablock + (size_t)kt * 16384;
#pragma unroll
        for (int it = 0; it < 4; it++)
            cpa16(sa + (uint32_t)(tid * 16 + it * 4096), ag + tid * 16 + it * 4096);
        int t = kt >> 4, chunk = kt & 15;
        int dy = t / 3, dx = t - dy * 3;
        const char* bg = Bimg + (dy * 66 + dx) * 2048 + chunk * 128;
        uint32_t sbB = sa + 16384u;
#pragma unroll
        for (int it = 0; it < 8; it++)
            cpa16(sbB + soff[it], bg + pixoff[it]);
        asm volatile("cp.async.commit_group;" ::: "memory");
    };

    load_tile(0, 0);
    load_tile(1, 1);
    load_tile(2, 2);

#pragma unroll 1
    for (int kt = 0; kt < NT; kt++) {
        if (kt < NT - 2)      asm volatile("cp.async.wait_group 2;" ::: "memory");
        else if (kt == NT - 2) asm volatile("cp.async.wait_group 1;" ::: "memory");
        else                   asm volatile("cp.async.wait_group 0;" ::: "memory");
        __syncthreads();

        const char* stg = sm + (kt & 3) * STAGE_BYTES;
        const char* aW = stg + warpM * 8192;
        const char* bW = stg + 16384 + (warpN * 64 + grp) * 32 + tig * 8;

#pragma unroll
        for (int ks = 0; ks < 4; ks++) {
            uint2 bf[8];
#pragma unroll
            for (int nf = 0; nf < 8; nf++)
                bf[nf] = *(const uint2*)(bW + ks * 8192 + nf * 256);
            uint4 af[4];
#pragma unroll
            for (int mf = 0; mf < 4; mf++)
                af[mf] = *(const uint4*)(aW + (mf * 4 + ks) * 512 + lane * 16);
#pragma unroll
            for (int mf = 0; mf < 4; mf++)
#pragma unroll
                for (int nf = 0; nf < 8; nf++)
                    mma8(acc[mf][nf], af[mf], bf[nf]);
        }
        if (kt + 3 < NT) load_tile(kt + 3, (kt + 3) & 3);
    }

    // ---------------- epilogue ----------------
    const float ns = nsp[0];
#pragma unroll
    for (int mf = 0; mf < 4; mf++) {
#pragma unroll
        for (int h2 = 0; h2 < 2; h2++) {
            int oc = ocb + warpM * 64 + mf * 16 + grp + h2 * 8;
            float inv = 1.f / g_sigma[(MODE * NB + n_img) * C + oc];
            float bias = bias_[oc];
            float sc = (MODE == 0) ? g_s[(1 * NB + n_img) * C + oc] : 0.f;
            int ocpos = (oc & ~7) | ((oc & 3) * 2 + ((oc >> 2) & 1));
#pragma unroll
            for (int nf = 0; nf < 8; nf++) {
                int pix = pix0 + warpN * 64 + nf * 8 + 2 * tig;
                float2 nz = *(const float2*)(noise + (size_t)n_img * PIX + pix);
                float v0 = acc[mf][nf][h2 * 2 + 0] * inv + bias + ns * nz.x;
                float v1 = acc[mf][nf][h2 * 2 + 1] * inv + bias + ns * nz.y;
                v0 = v0 > 0.f ? v0 : 0.2f * v0;
                v1 = v1 > 0.f ? v1 : 0.2f * v1;
                if (MODE == 0) {
                    int py = pix >> 6, px = pix & 63;
                    float* hb = g_h1p + (size_t)n_img * (66 * 66 * 512);
                    hb[((size_t)(py + 1) * 66 + (px + 1)) * 512 + ocpos] = tf32r(v0 * sc);
                    hb[((size_t)(py + 1) * 66 + (px + 2)) * 512 + ocpos] = tf32r(v1 * sc);
                } else {
                    *(float2*)(outp + ((size_t)(n_img * 512 + oc) * PIX) + pix) =
                        make_float2(v0, v1);
                }
            }
        }
    }
}

// ---------------------------------------------------------------------------
// K5: toRGB (1x1 modulated conv, no demod) + lrelu + bilinear 2x skip add
// ---------------------------------------------------------------------------
__device__ __forceinline__ void bl_coords(int Y, int& k0, int& k1, float& w0, float& w1) {
    if (Y & 1) { k0 = (Y - 1) >> 1; k1 = k0 + 1 < 31 ? k0 + 1 : 31; w0 = 0.75f; w1 = 0.25f; }
    else       { int k = Y >> 1; k0 = k - 1 > 0 ? k - 1 : 0; k1 = k; w0 = 0.25f; w1 = 0.75f; }
}

__global__ void k_rgb(const float* __restrict__ yimg, const float* __restrict__ rgb_w,
                      const float* __restrict__ rgb_b, float* __restrict__ out) {
    __shared__ float sw3[3][C];
    const int n = blockIdx.y;
    const int tid = threadIdx.x;
    for (int e = tid; e < 3 * C; e += 256) {
        int c = e >> 9, ci = e & 511;
        sw3[c][ci] = rgb_w[c * C + ci] * g_s[(2 * NB + n) * C + ci];
    }
    __syncthreads();

    const int px = blockIdx.x * 1024 + tid * 4;
    const float* h2 = out + (size_t)n * C * PIX;
    float a0x = 0, a0y = 0, a0z = 0, a0w = 0;
    float a1x = 0, a1y = 0, a1z = 0, a1w = 0;
    float a2x = 0, a2y = 0, a2z = 0, a2w = 0;
#pragma unroll 4
    for (int ci = 0; ci < C; ci++) {
        float4 hv = *(const float4*)(h2 + (size_t)ci * PIX + px);
        float w0 = sw3[0][ci], w1 = sw3[1][ci], w2 = sw3[2][ci];
        a0x = fmaf(hv.x, w0, a0x); a0y = fmaf(hv.y, w0, a0y);
        a0z = fmaf(hv.z, w0, a0z); a0w = fmaf(hv.w, w0, a0w);
        a1x = fmaf(hv.x, w1, a1x); a1y = fmaf(hv.y, w1, a1y);
        a1z = fmaf(hv.z, w1, a1z); a1w = fmaf(hv.w, w1, a1w);
        a2x = fmaf(hv.x, w2, a2x); a2y = fmaf(hv.y, w2, a2y);
        a2z = fmaf(hv.z, w2, a2z); a2w = fmaf(hv.w, w2, a2w);
    }

    float accv[3][4] = {{a0x, a0y, a0z, a0w}, {a1x, a1y, a1z, a1w}, {a2x, a2y, a2z, a2w}};
    const int Y = px >> 6;
    const int X0 = px & 63;
    int ky0, ky1; float wy0, wy1;
    bl_coords(Y, ky0, ky1, wy0, wy1);
    const size_t IMG_OFF = (size_t)NB * C * PIX;

#pragma unroll
    for (int c = 0; c < 3; c++) {
        float bias = rgb_b[c];
        const float* yb = yimg + (size_t)(n * 3 + c) * 32 * 32;
#pragma unroll
        for (int k = 0; k < 4; k++) {
            float r = accv[c][k] + bias;
            r = r > 0.f ? r : 0.2f * r;
            int X = X0 + k;
            int kx0, kx1; float wx0, wx1;
            bl_coords(X, kx0, kx1, wx0, wx1);
            float bv = wy0 * (wx0 * yb[ky0 * 32 + kx0] + wx1 * yb[ky0 * 32 + kx1])
                     + wy1 * (wx0 * yb[ky1 * 32 + kx0] + wx1 * yb[ky1 * 32 + kx1]);
            out[IMG_OFF + (size_t)(n * 3 + c) * PIX + px + k] = bv + r;
        }
    }
}

// ---------------------------------------------------------------------------
extern "C" void kernel_launch(void* const* d_in, const int* in_sizes, int n_in,
                              void* d_out, int out_size) {
    const float* x       = (const float*)d_in[0];
    const float* v       = (const float*)d_in[1];
    const float* yimg    = (const float*)d_in[2];
    const float* noise1  = (const float*)d_in[3];
    const float* noise2  = (const float*)d_in[4];
    const float* up_w    = (const float*)d_in[5];
    const float* up_b    = (const float*)d_in[6];
    const float* up_sw   = (const float*)d_in[7];
    const float* up_sb   = (const float*)d_in[8];
    const float* c_w     = (const float*)d_in[9];
    const float* c_b     = (const float*)d_in[10];
    const float* c_sw    = (const float*)d_in[11];
    const float* c_sb    = (const float*)d_in[12];
    const float* rgb_w   = (const float*)d_in[13];
    const float* rgb_b   = (const float*)d_in[14];
    const float* rgb_sw  = (const float*)d_in[15];
    const float* rgb_sb  = (const float*)d_in[16];
    const float* nsp     = (const float*)d_in[17];
    float* out = (float*)d_out;

    const int SMEM_GEMM = 4 * STAGE_BYTES;   // 192KB
    cudaFuncSetAttribute(k_gemm<0>, cudaFuncAttributeMaxDynamicSharedMemorySize, SMEM_GEMM);
    cudaFuncSetAttribute(k_gemm<1>, cudaFuncAttributeMaxDynamicSharedMemorySize, SMEM_GEMM);

    k_style<<<dim3(NB, 3), C>>>(v, up_sw, up_sb, c_sw, c_sb, rgb_sw, rgb_sb);
    k_wsq<<<2048, 256>>>(up_w, c_w);
    k_sigma<<<dim3(NB, 2), C>>>();
    k_dilate<<<17424, 256>>>(x);
    k_prepA2<<<18432, 256>>>(up_w, c_w);
    k_halo<<<1040, 256>>>();
    k_gemm<0><<<dim3(4, 128), 256, SMEM_GEMM>>>(up_b, noise1, nsp, out);
    k_gemm<1><<<dim3(4, 128), 256, SMEM_GEMM>>>(c_b, noise2, nsp, out);
    k_rgb<<<dim3(4, NB), 256>>>(yimg, rgb_w, rgb_b, out);
}

// round 9
// speedup vs baseline: 4.4539x; 1.4609x over previous
#include <cuda_runtime.h>
#include <cstdint>
#include <math.h>

#define NB 8
#define C 512
#define HO 64
#define PIX 4096
#define NT 144            // conv3: K tiles of 32

// ---------------- device scratch ------------------------------------------
// modulated x, channels-last perm, padded to 33x33 (row/col 32 = 0): [n][33][33][512]
__device__ __align__(128) float g_xp[(size_t)NB * 33 * 33 * 512];
// upconv out (modulated for conv3), padded 66x66 channels-last perm
__device__ __align__(128) float g_h1p[(size_t)NB * 66 * 66 * 512];
// fragment-layout weights: [mtile4][ktile144][mf8][ks4][lane32][e4]  (single tf32)
__device__ __align__(128) float g_Ac2[(size_t)4 * 144 * 4096];
__device__ __align__(128) float g_Au2[(size_t)4 * 144 * 4096];
__device__ float g_wsq_up[C * C];
__device__ float g_wsq_cT[C * C];
__device__ float g_s[3 * NB * C];
__device__ float g_sigma[2 * NB * C];

// subpixel class tables: global tapidx 0..8
__constant__ int c_T[9]  = {4, 3, 5, 1, 7, 0, 2, 6, 8};  // tap index into up_w [ky*3+kx]
__constant__ int c_OY[9] = {0, 0, 0, 1, 0, 1, 1, 0, 0};  // input row offset
__constant__ int c_OX[9] = {0, 1, 0, 0, 0, 1, 0, 1, 0};  // input col offset
__constant__ int c_KTB[4] = {0, 16, 48, 80};             // ktile base per class
__constant__ int c_NTC[4] = {16, 32, 32, 64};            // ktile count per class

// ---------------- helpers --------------------------------------------------
__device__ __forceinline__ uint32_t smem_u32(const void* p) {
    uint32_t a;
    asm("{ .reg .u64 t; cvta.to.shared.u64 t, %1; cvt.u32.u64 %0, t; }" : "=r"(a) : "l"(p));
    return a;
}
__device__ __forceinline__ float tf32r(float x) {
    uint32_t u;
    asm("cvt.rn.tf32.f32 %0, %1;" : "=r"(u) : "f"(x));
    return __uint_as_float(u);
}
__device__ __forceinline__ void cpa16(uint32_t s, const void* g) {
    asm volatile("cp.async.cg.shared.global [%0], [%1], 16;" :: "r"(s), "l"(g));
}
__device__ __forceinline__ void mma8(float* c, uint4 a, uint2 b) {
    asm volatile("mma.sync.aligned.m16n8k8.row.col.f32.tf32.tf32.f32 "
        "{%0,%1,%2,%3},{%4,%5,%6,%7},{%8,%9},{%0,%1,%2,%3};"
        : "+f"(c[0]), "+f"(c[1]), "+f"(c[2]), "+f"(c[3])
        : "r"(a.x), "r"(a.y), "r"(a.z), "r"(a.w), "r"(b.x), "r"(b.y));
}

// ---------------------------------------------------------------------------
// K0: weight-square tap sums (fp32 exact, for demod sigma)
// ---------------------------------------------------------------------------
__global__ void k_wsq(const float* __restrict__ up_w, const float* __restrict__ c_w) {
    int idx = blockIdx.x * blockDim.x + threadIdx.x;
    int which = idx >> 18;
    int p = idx & 262143;
    int i = p >> 9, o = p & 511;
    const float* src = which == 0 ? (up_w + ((i << 9) + o) * 9)
                                  : (c_w + ((o << 9) + i) * 9);
    float s = 0.f;
#pragma unroll
    for (int t = 0; t < 9; t++) s += src[t] * src[t];
    if (which == 0) g_wsq_up[p] = s;
    else            g_wsq_cT[p] = s;
}

// ---------------------------------------------------------------------------
// K1: style vectors s = v @ SW + SB
// ---------------------------------------------------------------------------
__global__ void k_style(const float* __restrict__ v,
                        const float* __restrict__ up_sw, const float* __restrict__ up_sb,
                        const float* __restrict__ c_sw,  const float* __restrict__ c_sb,
                        const float* __restrict__ rgb_sw,const float* __restrict__ rgb_sb) {
    int m = blockIdx.y, n = blockIdx.x, i = threadIdx.x;
    __shared__ float sv[C];
    sv[i] = v[n * C + i];
    __syncthreads();
    const float* SW = (m == 0) ? up_sw : (m == 1) ? c_sw : rgb_sw;
    const float* SB = (m == 0) ? up_sb : (m == 1) ? c_sb : rgb_sb;
    float acc = SB[i];
#pragma unroll 4
    for (int l = 0; l < C; l++) acc = fmaf(sv[l], SW[l * C + i], acc);
    g_s[(m * NB + n) * C + i] = acc;
}

// ---------------------------------------------------------------------------
// K2: demod sigma
// ---------------------------------------------------------------------------
__global__ void k_sigma(void) {
    int m = blockIdx.y, n = blockIdx.x, o = threadIdx.x;
    __shared__ float s2[C];
    float sv = g_s[(m * NB + n) * C + o];
    s2[o] = sv * sv;
    __syncthreads();
    const float* wsq = (m == 0) ? g_wsq_up : g_wsq_cT;
    float acc = 1e-8f;
#pragma unroll 4
    for (int i = 0; i < C; i++) acc = fmaf(s2[i], wsq[i * C + o], acc);
    g_sigma[(m * NB + n) * C + o] = sqrtf(acc);
}

// ---------------------------------------------------------------------------
// K3: modulated x -> g_xp channels-last perm {0,4,1,5,2,6,3,7}, 33x33 pad
// ---------------------------------------------------------------------------
__global__ void k_modx(const float* __restrict__ x) {
    size_t idx = (size_t)blockIdx.x * 256 + threadIdx.x;   // float4 over 8*33*33*128
    if (idx >= (size_t)NB * 33 * 33 * 128) return;
    int ci4 = (int)(idx & 127);
    int cell = (int)(idx >> 7);
    int xz = cell % 33; int t2 = cell / 33; int yz = t2 % 33; int nn = t2 / 33;
    float4 v = make_float4(0.f, 0.f, 0.f, 0.f);
    if (yz < 32 && xz < 32) {
        int g = (ci4 >> 1) * 8;
        int hi = ci4 & 1;
        int c0 = g + (hi ? 2 : 0), c1 = g + (hi ? 6 : 4);
        int c2 = g + (hi ? 3 : 1), c3 = g + (hi ? 7 : 5);
        const float* sp = g_s + (0 * NB + nn) * C;
        const float* xp = x + (((size_t)nn * 512) * 32 + yz) * 32 + xz;
        v.x = tf32r(xp[(size_t)c0 * 1024] * sp[c0]);
        v.y = tf32r(xp[(size_t)c1 * 1024] * sp[c1]);
        v.z = tf32r(xp[(size_t)c2 * 1024] * sp[c2]);
        v.w = tf32r(xp[(size_t)c3 * 1024] * sp[c3]);
    }
    ((float4*)g_xp)[idx] = v;
}

// ---------------------------------------------------------------------------
// K3b: zero the halo of g_h1p
// ---------------------------------------------------------------------------
__global__ void k_halo(void) {
    int idx = blockIdx.x * 256 + threadIdx.x;   // 8*260*128
    if (idx >= NB * 260 * 128) return;
    int ci4 = idx & 127;
    int c2 = idx >> 7;
    int h = c2 % 260, nn = c2 / 260;
    int yz, xz;
    if (h < 66)       { yz = 0;  xz = h; }
    else if (h < 132) { yz = 65; xz = h - 66; }
    else { int rem = h - 132; yz = 1 + (rem >> 1); xz = (rem & 1) * 65; }
    ((float4*)g_h1p)[((size_t)(nn * 66 + yz) * 66 + xz) * 128 + ci4] =
        make_float4(0.f, 0.f, 0.f, 0.f);
}

// ---------------------------------------------------------------------------
// K3c: weights -> fragment layout, single tf32 (RN).
//   flat off = (((mtile*144+kt)*8+mf)*4+ks)*128 + lane*4 + e
//   element: m = mf*16 + (lane>>2) + (e&1)*8 ; kk = ks*8 + (lane&3) + (e>>1)*4
//   conv3 : kt = (t, ci-chunk): w = c_w[oc][ci][t], ci = (kt%16)*32+kk, t = kt/16
//   upconv: kt = (class,tap,ci-chunk): tapidx = kt>>4, ci = (kt&15)*32+kk,
//           w = up_w[ci][oc][c_T[tapidx]]  (subpixel taps, no flip)
// ---------------------------------------------------------------------------
#define AFRAG_ELEMS 2359296
__global__ void k_prepA2(const float* __restrict__ up_w, const float* __restrict__ c_w) {
    int idx = blockIdx.x * 256 + threadIdx.x;   // 0 .. 2*2359296
    int which = idx >= AFRAG_ELEMS;
    int off = which ? idx - AFRAG_ELEMS : idx;
    int e = off & 3, lane = (off >> 2) & 31, ks = (off >> 7) & 3;
    int mf = (off >> 9) & 7;
    int rest = off >> 12;
    int kt = rest % 144, mtile = rest / 144;
    int grp = lane >> 2, tig = lane & 3;
    int m = mf * 16 + grp + (e & 1) * 8;
    int kk = ks * 8 + tig + (e >> 1) * 4;
    int oc = mtile * 128 + m;
    float w;
    if (which) {
        int tapidx = kt >> 4;
        int ci = (kt & 15) * 32 + kk;
        w = up_w[((size_t)ci * 512 + oc) * 9 + c_T[tapidx]];
    } else {
        int kg = kt * 32 + kk;
        int t = kg >> 9, ci = kg & 511;
        w = c_w[((size_t)oc * 512 + ci) * 9 + t];
    }
    float val = tf32r(w);
    if (which) g_Au2[off] = val;
    else       g_Ac2[off] = val;
}

#define STAGE_BYTES 49152   // 16KB A + 32KB B

// ---------------------------------------------------------------------------
// K4a: upconv subpixel GEMM. blockIdx: (mtile4, img8 x Nblk4, class4).
// Each class cls=(dy,dx) computes out(2a+dy, 2b+dx) for a,b in 32x32 grid;
// CTA tile: M=128 oc x N=256 grid-px (8 a-rows x 32 b-cols), K = c_NTC[cls]*32.
// Epilogue: /sigma0 + up_b + ns*noise1, lrelu, *s_c, tf32 -> g_h1p interior.
// ---------------------------------------------------------------------------
__global__ void __launch_bounds__(256)
k_gemmU(const float* __restrict__ bias_, const float* __restrict__ noise,
        const float* __restrict__ nsp) {
    extern __shared__ char sm[];
    const int tid = threadIdx.x;
    const int wid = tid >> 5, lane = tid & 31;
    const int warpM = wid >> 2, warpN = wid & 3;
    const int grp = lane >> 2, tig = lane & 3;

    const int mtile = blockIdx.x;
    const int ocb = mtile << 7;
    const int n_img = blockIdx.y >> 2;
    const int a0 = (blockIdx.y & 3) * 8;
    const int cls = blockIdx.z;
    const int dy = cls >> 1, dx = cls & 1;
    const int ktb = c_KTB[cls];
    const int NTc = c_NTC[cls];

    const char* Ablock = (const char*)g_Au2 + (size_t)mtile * 144 * 16384;
    const char* Bimg = (const char*)g_xp + (size_t)n_img * (33 * 33 * 512) * 4;
    const uint32_t sb = smem_u32(sm);

    // per-thread B copy offsets (pixel part, without tap offset)
    uint32_t pixoff[8], soff[8];
#pragma unroll
    for (int it = 0; it < 8; it++) {
        int c = tid + 256 * it;
        int nn = c >> 3, r = c & 7;
        int py = a0 + (nn >> 5), px = nn & 31;
        pixoff[it] = (uint32_t)(py * 33 + px) * 2048u + (uint32_t)r * 16u;
        soff[it] = (uint32_t)((r >> 1) * 8192 + nn * 32 + (r & 1) * 16);
    }

    float acc[4][8][4];
#pragma unroll
    for (int a = 0; a < 4; a++)
#pragma unroll
        for (int b = 0; b < 8; b++)
#pragma unroll
            for (int e = 0; e < 4; e++) acc[a][b][e] = 0.f;

    auto load_tile = [&](int ktl, int s) {
        int kt = ktb + ktl;
        uint32_t sa = sb + (uint32_t)s * STAGE_BYTES;
        const char* ag = Ablock + (size_t)kt * 16384;
#pragma unroll
        for (int it = 0; it < 4; it++)
            cpa16(sa + (uint32_t)(tid * 16 + it * 4096), ag + tid * 16 + it * 4096);
        int tapidx = kt >> 4, chunk = kt & 15;
        const char* bg = Bimg + (c_OY[tapidx] * 33 + c_OX[tapidx]) * 2048 + chunk * 128;
        uint32_t sbB = sa + 16384u;
#pragma unroll
        for (int it = 0; it < 8; it++)
            cpa16(sbB + soff[it], bg + pixoff[it]);
        asm volatile("cp.async.commit_group;" ::: "memory");
    };

    load_tile(0, 0);
    load_tile(1, 1);
    load_tile(2, 2);

#pragma unroll 1
    for (int kt = 0; kt < NTc; kt++) {
        if (kt < NTc - 2)       asm volatile("cp.async.wait_group 2;" ::: "memory");
        else if (kt == NTc - 2) asm volatile("cp.async.wait_group 1;" ::: "memory");
        else                    asm volatile("cp.async.wait_group 0;" ::: "memory");
        __syncthreads();

        const char* stg = sm + (kt & 3) * STAGE_BYTES;
        const char* aW = stg + warpM * 8192;
        const char* bW = stg + 16384 + (warpN * 64 + grp) * 32 + tig * 8;

#pragma unroll
        for (int ks = 0; ks < 4; ks++) {
            uint2 bf[8];
#pragma unroll
            for (int nf = 0; nf < 8; nf++)
                bf[nf] = *(const uint2*)(bW + ks * 8192 + nf * 256);
            uint4 af[4];
#pragma unroll
            for (int mf = 0; mf < 4; mf++)
                af[mf] = *(const uint4*)(aW + (mf * 4 + ks) * 512 + lane * 16);
#pragma unroll
            for (int mf = 0; mf < 4; mf++)
#pragma unroll
                for (int nf = 0; nf < 8; nf++)
                    mma8(acc[mf][nf], af[mf], bf[nf]);
        }
        if (kt + 3 < NTc) load_tile(kt + 3, (kt + 3) & 3);
    }

    // ---------------- epilogue: scatter to parity class ----------------
    const float ns = nsp[0];
    float* hb = g_h1p + (size_t)n_img * (66 * 66 * 512);
    const float* nzb = noise + (size_t)n_img * PIX;
#pragma unroll
    for (int mf = 0; mf < 4; mf++) {
#pragma unroll
        for (int h2 = 0; h2 < 2; h2++) {
            int oc = ocb + warpM * 64 + mf * 16 + grp + h2 * 8;
            float inv = 1.f / g_sigma[(0 * NB + n_img) * C + oc];
            float bias = bias_[oc];
            float sc = g_s[(1 * NB + n_img) * C + oc];
            int ocpos = (oc & ~7) | ((oc & 3) * 2 + ((oc >> 2) & 1));
#pragma unroll
            for (int nf = 0; nf < 8; nf++) {
                int pig = warpN * 64 + nf * 8 + 2 * tig;     // 0..255 grid px
                int a = a0 + (pig >> 5);
                int b = pig & 31;
                int y = 2 * a + dy;
                int x0 = 2 * b + dx, x1 = x0 + 2;
                float v0 = acc[mf][nf][h2 * 2 + 0] * inv + bias + ns * nzb[y * HO + x0];
                float v1 = acc[mf][nf][h2 * 2 + 1] * inv + bias + ns * nzb[y * HO + x1];
                v0 = v0 > 0.f ? v0 : 0.2f * v0;
                v1 = v1 > 0.f ? v1 : 0.2f * v1;
                hb[((size_t)(y + 1) * 66 + (x0 + 1)) * 512 + ocpos] = tf32r(v0 * sc);
                hb[((size_t)(y + 1) * 66 + (x1 + 1)) * 512 + ocpos] = tf32r(v1 * sc);
            }
        }
    }
}

// ---------------------------------------------------------------------------
// K4b: conv3 GEMM (unchanged from R8). M=128 oc x N=256 px, K=4608.
// ---------------------------------------------------------------------------
__global__ void __launch_bounds__(256)
k_gemmC(const float* __restrict__ bias_, const float* __restrict__ noise,
        const float* __restrict__ nsp, float* __restrict__ outp) {
    extern __shared__ char sm[];
    const int tid = threadIdx.x;
    const int wid = tid >> 5, lane = tid & 31;
    const int warpM = wid >> 2, warpN = wid & 3;
    const int grp = lane >> 2, tig = lane & 3;

    const int mtile = blockIdx.x;
    const int ocb = mtile << 7;
    const int n_img = blockIdx.y >> 4;
    const int blk = blockIdx.y & 15;
    const int pix0 = blk << 8;
    const int y0 = pix0 >> 6;

    const char* Ablock = (const char*)g_Ac2 + (size_t)mtile * 144 * 16384;
    const char* Bimg = (const char*)g_h1p + (size_t)n_img * (66 * 66 * 512) * 4;
    const uint32_t sb = smem_u32(sm);

    uint32_t pixoff[8], soff[8];
#pragma unroll
    for (int it = 0; it < 8; it++) {
        int c = tid + 256 * it;
        int nn = c >> 3, r = c & 7;
        int py = y0 + (nn >> 6), px = nn & 63;
        pixoff[it] = (uint32_t)(py * 66 + px) * 2048u + (uint32_t)r * 16u;
        soff[it] = (uint32_t)((r >> 1) * 8192 + nn * 32 + (r & 1) * 16);
    }

    float acc[4][8][4];
#pragma unroll
    for (int a = 0; a < 4; a++)
#pragma unroll
        for (int b = 0; b < 8; b++)
#pragma unroll
            for (int e = 0; e < 4; e++) acc[a][b][e] = 0.f;

    auto load_tile = [&](int kt, int s) {
        uint32_t sa = sb + (uint32_t)s * STAGE_BYTES;
        const char* ag = Ablock + (size_t)kt * 16384;
#pragma unroll
        for (int it = 0; it < 4; it++)
            cpa16(sa + (uint32_t)(tid * 16 + it * 4096), ag + tid * 16 + it * 4096);
        int t = kt >> 4, chunk = kt & 15;
        int dy = t / 3, dx = t - dy * 3;
        const char* bg = Bimg + (dy * 66 + dx) * 2048 + chunk * 128;
        uint32_t sbB = sa + 16384u;
#pragma unroll
        for (int it = 0; it < 8; it++)
            cpa16(sbB + soff[it], bg + pixoff[it]);
        asm volatile("cp.async.commit_group;" ::: "memory");
    };

    load_tile(0, 0);
    load_tile(1, 1);
    load_tile(2, 2);

#pragma unroll 1
    for (int kt = 0; kt < NT; kt++) {
        if (kt < NT - 2)       asm volatile("cp.async.wait_group 2;" ::: "memory");
        else if (kt == NT - 2) asm volatile("cp.async.wait_group 1;" ::: "memory");
        else                   asm volatile("cp.async.wait_group 0;" ::: "memory");
        __syncthreads();

        const char* stg = sm + (kt & 3) * STAGE_BYTES;
        const char* aW = stg + warpM * 8192;
        const char* bW = stg + 16384 + (warpN * 64 + grp) * 32 + tig * 8;

#pragma unroll
        for (int ks = 0; ks < 4; ks++) {
            uint2 bf[8];
#pragma unroll
            for (int nf = 0; nf < 8; nf++)
                bf[nf] = *(const uint2*)(bW + ks * 8192 + nf * 256);
            uint4 af[4];
#pragma unroll
            for (int mf = 0; mf < 4; mf++)
                af[mf] = *(const uint4*)(aW + (mf * 4 + ks) * 512 + lane * 16);
#pragma unroll
            for (int mf = 0; mf < 4; mf++)
#pragma unroll
                for (int nf = 0; nf < 8; nf++)
                    mma8(acc[mf][nf], af[mf], bf[nf]);
        }
        if (kt + 3 < NT) load_tile(kt + 3, (kt + 3) & 3);
    }

    const float ns = nsp[0];
#pragma unroll
    for (int mf = 0; mf < 4; mf++) {
#pragma unroll
        for (int h2 = 0; h2 < 2; h2++) {
            int oc = ocb + warpM * 64 + mf * 16 + grp + h2 * 8;
            float inv = 1.f / g_sigma[(1 * NB + n_img) * C + oc];
            float bias = bias_[oc];
#pragma unroll
            for (int nf = 0; nf < 8; nf++) {
                int pix = pix0 + warpN * 64 + nf * 8 + 2 * tig;
                float2 nz = *(const float2*)(noise + (size_t)n_img * PIX + pix);
                float v0 = acc[mf][nf][h2 * 2 + 0] * inv + bias + ns * nz.x;
                float v1 = acc[mf][nf][h2 * 2 + 1] * inv + bias + ns * nz.y;
                v0 = v0 > 0.f ? v0 : 0.2f * v0;
                v1 = v1 > 0.f ? v1 : 0.2f * v1;
                *(float2*)(outp + ((size_t)(n_img * 512 + oc) * PIX) + pix) =
                    make_float2(v0, v1);
            }
        }
    }
}

// ---------------------------------------------------------------------------
// K5: toRGB (1x1 modulated conv, no demod) + lrelu + bilinear 2x skip add
// ---------------------------------------------------------------------------
__device__ __forceinline__ void bl_coords(int Y, int& k0, int& k1, float& w0, float& w1) {
    if (Y & 1) { k0 = (Y - 1) >> 1; k1 = k0 + 1 < 31 ? k0 + 1 : 31; w0 = 0.75f; w1 = 0.25f; }
    else       { int k = Y >> 1; k0 = k - 1 > 0 ? k - 1 : 0; k1 = k; w0 = 0.25f; w1 = 0.75f; }
}

__global__ void k_rgb(const float* __restrict__ yimg, const float* __restrict__ rgb_w,
                      const float* __restrict__ rgb_b, float* __restrict__ out) {
    __shared__ float sw3[3][C];
    const int n = blockIdx.y;
    const int tid = threadIdx.x;
    for (int e = tid; e < 3 * C; e += 256) {
        int c = e >> 9, ci = e & 511;
        sw3[c][ci] = rgb_w[c * C + ci] * g_s[(2 * NB + n) * C + ci];
    }
    __syncthreads();

    const int px = blockIdx.x * 1024 + tid * 4;
    const float* h2 = out + (size_t)n * C * PIX;
    float a0x = 0, a0y = 0, a0z = 0, a0w = 0;
    float a1x = 0, a1y = 0, a1z = 0, a1w = 0;
    float a2x = 0, a2y = 0, a2z = 0, a2w = 0;
#pragma unroll 4
    for (int ci = 0; ci < C; ci++) {
        float4 hv = *(const float4*)(h2 + (size_t)ci * PIX + px);
        float w0 = sw3[0][ci], w1 = sw3[1][ci], w2 = sw3[2][ci];
        a0x = fmaf(hv.x, w0, a0x); a0y = fmaf(hv.y, w0, a0y);
        a0z = fmaf(hv.z, w0, a0z); a0w = fmaf(hv.w, w0, a0w);
        a1x = fmaf(hv.x, w1, a1x); a1y = fmaf(hv.y, w1, a1y);
        a1z = fmaf(hv.z, w1, a1z); a1w = fmaf(hv.w, w1, a1w);
        a2x = fmaf(hv.x, w2, a2x); a2y = fmaf(hv.y, w2, a2y);
        a2z = fmaf(hv.z, w2, a2z); a2w = fmaf(hv.w, w2, a2w);
    }

    float accv[3][4] = {{a0x, a0y, a0z, a0w}, {a1x, a1y, a1z, a1w}, {a2x, a2y, a2z, a2w}};
    const int Y = px >> 6;
    const int X0 = px & 63;
    int ky0, ky1; float wy0, wy1;
    bl_coords(Y, ky0, ky1, wy0, wy1);
    const size_t IMG_OFF = (size_t)NB * C * PIX;

#pragma unroll
    for (int c = 0; c < 3; c++) {
        float bias = rgb_b[c];
        const float* yb = yimg + (size_t)(n * 3 + c) * 32 * 32;
#pragma unroll
        for (int k = 0; k < 4; k++) {
            float r = accv[c][k] + bias;
            r = r > 0.f ? r : 0.2f * r;
            int X = X0 + k;
            int kx0, kx1; float wx0, wx1;
            bl_coords(X, kx0, kx1, wx0, wx1);
            float bv = wy0 * (wx0 * yb[ky0 * 32 + kx0] + wx1 * yb[ky0 * 32 + kx1])
                     + wy1 * (wx0 * yb[ky1 * 32 + kx0] + wx1 * yb[ky1 * 32 + kx1]);
            out[IMG_OFF + (size_t)(n * 3 + c) * PIX + px + k] = bv + r;
        }
    }
}

// ---------------------------------------------------------------------------
extern "C" void kernel_launch(void* const* d_in, const int* in_sizes, int n_in,
                              void* d_out, int out_size) {
    const float* x       = (const float*)d_in[0];
    const float* v       = (const float*)d_in[1];
    const float* yimg    = (const float*)d_in[2];
    const float* noise1  = (const float*)d_in[3];
    const float* noise2  = (const float*)d_in[4];
    const float* up_w    = (const float*)d_in[5];
    const float* up_b    = (const float*)d_in[6];
    const float* up_sw   = (const float*)d_in[7];
    const float* up_sb   = (const float*)d_in[8];
    const float* c_w     = (const float*)d_in[9];
    const float* c_b     = (const float*)d_in[10];
    const float* c_sw    = (const float*)d_in[11];
    const float* c_sb    = (const float*)d_in[12];
    const float* rgb_w   = (const float*)d_in[13];
    const float* rgb_b   = (const float*)d_in[14];
    const float* rgb_sw  = (const float*)d_in[15];
    const float* rgb_sb  = (const float*)d_in[16];
    const float* nsp     = (const float*)d_in[17];
    float* out = (float*)d_out;

    const int SMEM_GEMM = 4 * STAGE_BYTES;   // 192KB
    cudaFuncSetAttribute(k_gemmU, cudaFuncAttributeMaxDynamicSharedMemorySize, SMEM_GEMM);
    cudaFuncSetAttribute(k_gemmC, cudaFuncAttributeMaxDynamicSharedMemorySize, SMEM_GEMM);

    k_style<<<dim3(NB, 3), C>>>(v, up_sw, up_sb, c_sw, c_sb, rgb_sw, rgb_sb);
    k_wsq<<<2048, 256>>>(up_w, c_w);
    k_sigma<<<dim3(NB, 2), C>>>();
    k_modx<<<4357, 256>>>(x);
    k_prepA2<<<18432, 256>>>(up_w, c_w);
    k_halo<<<1040, 256>>>();
    k_gemmU<<<dim3(4, 32, 4), 256, SMEM_GEMM>>>(up_b, noise1, nsp);
    k_gemmC<<<dim3(4, 128), 256, SMEM_GEMM>>>(c_b, noise2, nsp, out);
    k_rgb<<<dim3(4, NB), 256>>>(yimg, rgb_w, rgb_b, out);
}

// round 10
// speedup vs baseline: 4.6212x; 1.0376x over previous
#include <cuda_runtime.h>
#include <cstdint>
#include <math.h>

#define NB 8
#define C 512
#define HO 64
#define PIX 4096
#define NT 144            // conv3: K tiles of 32

// ---------------- device scratch ------------------------------------------
// modulated x, channels-last perm, padded to 33x33 (row/col 32 = 0): [n][33][33][512]
__device__ __align__(128) float g_xp[(size_t)NB * 33 * 33 * 512];
// upconv out (modulated for conv3), padded 66x66 channels-last perm
__device__ __align__(128) float g_h1p[(size_t)NB * 66 * 66 * 512];
// fragment-layout weights: [mtile4][ktile144][mf8][ks4][lane32][e4]  (single tf32)
__device__ __align__(128) float g_Ac2[(size_t)4 * 144 * 4096];
__device__ __align__(128) float g_Au2[(size_t)4 * 144 * 4096];
__device__ float g_wsq_up[C * C];
__device__ float g_wsq_cT[C * C];
__device__ float g_s[3 * NB * C];
__device__ float g_sigma[2 * NB * C];

// subpixel class tables: global tapidx 0..8
__constant__ int c_T[9]  = {4, 3, 5, 1, 7, 0, 2, 6, 8};  // tap index into up_w [ky*3+kx]
__constant__ int c_OY[9] = {0, 0, 0, 1, 0, 1, 1, 0, 0};  // input row offset
__constant__ int c_OX[9] = {0, 1, 0, 0, 0, 1, 0, 1, 0};  // input col offset
__constant__ int c_KTB[4] = {0, 16, 48, 80};             // ktile base per class
__constant__ int c_NTC[4] = {16, 32, 32, 64};            // ktile count per class

// ---------------- helpers --------------------------------------------------
__device__ __forceinline__ uint32_t smem_u32(const void* p) {
    uint32_t a;
    asm("{ .reg .u64 t; cvta.to.shared.u64 t, %1; cvt.u32.u64 %0, t; }" : "=r"(a) : "l"(p));
    return a;
}
__device__ __forceinline__ float tf32r(float x) {
    uint32_t u;
    asm("cvt.rn.tf32.f32 %0, %1;" : "=r"(u) : "f"(x));
    return __uint_as_float(u);
}
__device__ __forceinline__ void cpa16(uint32_t s, const void* g) {
    asm volatile("cp.async.cg.shared.global [%0], [%1], 16;" :: "r"(s), "l"(g));
}
__device__ __forceinline__ void mma8(float* c, uint4 a, uint2 b) {
    asm volatile("mma.sync.aligned.m16n8k8.row.col.f32.tf32.tf32.f32 "
        "{%0,%1,%2,%3},{%4,%5,%6,%7},{%8,%9},{%0,%1,%2,%3};"
        : "+f"(c[0]), "+f"(c[1]), "+f"(c[2]), "+f"(c[3])
        : "r"(a.x), "r"(a.y), "r"(a.z), "r"(a.w), "r"(b.x), "r"(b.y));
}

// ---------------------------------------------------------------------------
// K0: weight-square tap sums (fp32 exact, for demod sigma)
// ---------------------------------------------------------------------------
__global__ void k_wsq(const float* __restrict__ up_w, const float* __restrict__ c_w) {
    int idx = blockIdx.x * blockDim.x + threadIdx.x;
    int which = idx >> 18;
    int p = idx & 262143;
    int i = p >> 9, o = p & 511;
    const float* src = which == 0 ? (up_w + ((i << 9) + o) * 9)
                                  : (c_w + ((o << 9) + i) * 9);
    float s = 0.f;
#pragma unroll
    for (int t = 0; t < 9; t++) s += src[t] * src[t];
    if (which == 0) g_wsq_up[p] = s;
    else            g_wsq_cT[p] = s;
}

// ---------------------------------------------------------------------------
// K1: style vectors s = v @ SW + SB
// ---------------------------------------------------------------------------
__global__ void k_style(const float* __restrict__ v,
                        const float* __restrict__ up_sw, const float* __restrict__ up_sb,
                        const float* __restrict__ c_sw,  const float* __restrict__ c_sb,
                        const float* __restrict__ rgb_sw,const float* __restrict__ rgb_sb) {
    int m = blockIdx.y, n = blockIdx.x, i = threadIdx.x;
    __shared__ float sv[C];
    sv[i] = v[n * C + i];
    __syncthreads();
    const float* SW = (m == 0) ? up_sw : (m == 1) ? c_sw : rgb_sw;
    const float* SB = (m == 0) ? up_sb : (m == 1) ? c_sb : rgb_sb;
    float acc = SB[i];
#pragma unroll 4
    for (int l = 0; l < C; l++) acc = fmaf(sv[l], SW[l * C + i], acc);
    g_s[(m * NB + n) * C + i] = acc;
}

// ---------------------------------------------------------------------------
// K2: demod sigma
// ---------------------------------------------------------------------------
__global__ void k_sigma(void) {
    int m = blockIdx.y, n = blockIdx.x, o = threadIdx.x;
    __shared__ float s2[C];
    float sv = g_s[(m * NB + n) * C + o];
    s2[o] = sv * sv;
    __syncthreads();
    const float* wsq = (m == 0) ? g_wsq_up : g_wsq_cT;
    float acc = 1e-8f;
#pragma unroll 4
    for (int i = 0; i < C; i++) acc = fmaf(s2[i], wsq[i * C + o], acc);
    g_sigma[(m * NB + n) * C + o] = sqrtf(acc);
}

// ---------------------------------------------------------------------------
// K3: modulated x -> g_xp channels-last perm {0,4,1,5,2,6,3,7}, 33x33 pad
// ---------------------------------------------------------------------------
__global__ void k_modx(const float* __restrict__ x) {
    size_t idx = (size_t)blockIdx.x * 256 + threadIdx.x;   // float4 over 8*33*33*128
    if (idx >= (size_t)NB * 33 * 33 * 128) return;
    int ci4 = (int)(idx & 127);
    int cell = (int)(idx >> 7);
    int xz = cell % 33; int t2 = cell / 33; int yz = t2 % 33; int nn = t2 / 33;
    float4 v = make_float4(0.f, 0.f, 0.f, 0.f);
    if (yz < 32 && xz < 32) {
        int g = (ci4 >> 1) * 8;
        int hi = ci4 & 1;
        int c0 = g + (hi ? 2 : 0), c1 = g + (hi ? 6 : 4);
        int c2 = g + (hi ? 3 : 1), c3 = g + (hi ? 7 : 5);
        const float* sp = g_s + (0 * NB + nn) * C;
        const float* xp = x + (((size_t)nn * 512) * 32 + yz) * 32 + xz;
        v.x = tf32r(xp[(size_t)c0 * 1024] * sp[c0]);
        v.y = tf32r(xp[(size_t)c1 * 1024] * sp[c1]);
        v.z = tf32r(xp[(size_t)c2 * 1024] * sp[c2]);
        v.w = tf32r(xp[(size_t)c3 * 1024] * sp[c3]);
    }
    ((float4*)g_xp)[idx] = v;
}

// ---------------------------------------------------------------------------
// K3b: zero the halo of g_h1p
// ---------------------------------------------------------------------------
__global__ void k_halo(void) {
    int idx = blockIdx.x * 256 + threadIdx.x;   // 8*260*128
    if (idx >= NB * 260 * 128) return;
    int ci4 = idx & 127;
    int c2 = idx >> 7;
    int h = c2 % 260, nn = c2 / 260;
    int yz, xz;
    if (h < 66)       { yz = 0;  xz = h; }
    else if (h < 132) { yz = 65; xz = h - 66; }
    else { int rem = h - 132; yz = 1 + (rem >> 1); xz = (rem & 1) * 65; }
    ((float4*)g_h1p)[((size_t)(nn * 66 + yz) * 66 + xz) * 128 + ci4] =
        make_float4(0.f, 0.f, 0.f, 0.f);
}

// ---------------------------------------------------------------------------
// K3c: weights -> fragment layout, single tf32 (RN).
// ---------------------------------------------------------------------------
#define AFRAG_ELEMS 2359296
__global__ void k_prepA2(const float* __restrict__ up_w, const float* __restrict__ c_w) {
    int idx = blockIdx.x * 256 + threadIdx.x;   // 0 .. 2*2359296
    int which = idx >= AFRAG_ELEMS;
    int off = which ? idx - AFRAG_ELEMS : idx;
    int e = off & 3, lane = (off >> 2) & 31, ks = (off >> 7) & 3;
    int mf = (off >> 9) & 7;
    int rest = off >> 12;
    int kt = rest % 144, mtile = rest / 144;
    int grp = lane >> 2, tig = lane & 3;
    int m = mf * 16 + grp + (e & 1) * 8;
    int kk = ks * 8 + tig + (e >> 1) * 4;
    int oc = mtile * 128 + m;
    float w;
    if (which) {
        int tapidx = kt >> 4;
        int ci = (kt & 15) * 32 + kk;
        w = up_w[((size_t)ci * 512 + oc) * 9 + c_T[tapidx]];
    } else {
        int kg = kt * 32 + kk;
        int t = kg >> 9, ci = kg & 511;
        w = c_w[((size_t)oc * 512 + ci) * 9 + t];
    }
    float val = tf32r(w);
    if (which) g_Au2[off] = val;
    else       g_Ac2[off] = val;
}

#define STAGE_BYTES 49152   // 16KB A + 32KB B
#define NTHR 512            // 16 warps: 4 M-groups x 4 N-groups, warp tile 32x64

// ---------------------------------------------------------------------------
// K4a: upconv subpixel GEMM (16-warp version).
// ---------------------------------------------------------------------------
__global__ void __launch_bounds__(NTHR)
k_gemmU(const float* __restrict__ bias_, const float* __restrict__ noise,
        const float* __restrict__ nsp) {
    extern __shared__ char sm[];
    const int tid = threadIdx.x;
    const int wid = tid >> 5, lane = tid & 31;
    const int warpM = wid >> 2, warpN = wid & 3;   // 4 x 4
    const int grp = lane >> 2, tig = lane & 3;

    const int mtile = blockIdx.x;
    const int ocb = mtile << 7;
    const int n_img = blockIdx.y >> 2;
    const int a0 = (blockIdx.y & 3) * 8;
    const int cls = blockIdx.z;
    const int dy = cls >> 1, dx = cls & 1;
    const int ktb = c_KTB[cls];
    const int NTc = c_NTC[cls];

    const char* Ablock = (const char*)g_Au2 + (size_t)mtile * 144 * 16384;
    const char* Bimg = (const char*)g_xp + (size_t)n_img * (33 * 33 * 512) * 4;
    const uint32_t sb = smem_u32(sm);

    // per-thread B copy offsets (4 x 16B with 512 threads)
    uint32_t pixoff[4], soff[4];
#pragma unroll
    for (int it = 0; it < 4; it++) {
        int c = tid + NTHR * it;
        int nn = c >> 3, r = c & 7;
        int py = a0 + (nn >> 5), px = nn & 31;
        pixoff[it] = (uint32_t)(py * 33 + px) * 2048u + (uint32_t)r * 16u;
        soff[it] = (uint32_t)((r >> 1) * 8192 + nn * 32 + (r & 1) * 16);
    }

    float acc[2][8][4];
#pragma unroll
    for (int a = 0; a < 2; a++)
#pragma unroll
        for (int b = 0; b < 8; b++)
#pragma unroll
            for (int e = 0; e < 4; e++) acc[a][b][e] = 0.f;

    auto load_tile = [&](int ktl, int s) {
        int kt = ktb + ktl;
        uint32_t sa = sb + (uint32_t)s * STAGE_BYTES;
        const char* ag = Ablock + (size_t)kt * 16384;
#pragma unroll
        for (int it = 0; it < 2; it++)
            cpa16(sa + (uint32_t)(tid * 16 + it * 8192), ag + tid * 16 + it * 8192);
        int tapidx = kt >> 4, chunk = kt & 15;
        const char* bg = Bimg + (c_OY[tapidx] * 33 + c_OX[tapidx]) * 2048 + chunk * 128;
        uint32_t sbB = sa + 16384u;
#pragma unroll
        for (int it = 0; it < 4; it++)
            cpa16(sbB + soff[it], bg + pixoff[it]);
        asm volatile("cp.async.commit_group;" ::: "memory");
    };

    load_tile(0, 0);
    load_tile(1, 1);
    load_tile(2, 2);

#pragma unroll 1
    for (int kt = 0; kt < NTc; kt++) {
        if (kt < NTc - 2)       asm volatile("cp.async.wait_group 2;" ::: "memory");
        else if (kt == NTc - 2) asm volatile("cp.async.wait_group 1;" ::: "memory");
        else                    asm volatile("cp.async.wait_group 0;" ::: "memory");
        __syncthreads();

        const char* stg = sm + (kt & 3) * STAGE_BYTES;
        const char* aW = stg;
        const char* bW = stg + 16384 + (warpN * 64 + grp) * 32 + tig * 8;

#pragma unroll
        for (int ks = 0; ks < 4; ks++) {
            uint2 bf[8];
#pragma unroll
            for (int nf = 0; nf < 8; nf++)
                bf[nf] = *(const uint2*)(bW + ks * 8192 + nf * 256);
            uint4 af[2];
#pragma unroll
            for (int mf = 0; mf < 2; mf++)
                af[mf] = *(const uint4*)(aW + ((warpM * 2 + mf) * 4 + ks) * 512 + lane * 16);
#pragma unroll
            for (int mf = 0; mf < 2; mf++)
#pragma unroll
                for (int nf = 0; nf < 8; nf++)
                    mma8(acc[mf][nf], af[mf], bf[nf]);
        }
        if (kt + 3 < NTc) load_tile(kt + 3, (kt + 3) & 3);
    }

    // ---------------- epilogue: scatter to parity class ----------------
    const float ns = nsp[0];
    float* hb = g_h1p + (size_t)n_img * (66 * 66 * 512);
    const float* nzb = noise + (size_t)n_img * PIX;
#pragma unroll
    for (int mf = 0; mf < 2; mf++) {
#pragma unroll
        for (int h2 = 0; h2 < 2; h2++) {
            int oc = ocb + warpM * 32 + mf * 16 + grp + h2 * 8;
            float inv = 1.f / g_sigma[(0 * NB + n_img) * C + oc];
            float bias = bias_[oc];
            float sc = g_s[(1 * NB + n_img) * C + oc];
            int ocpos = (oc & ~7) | ((oc & 3) * 2 + ((oc >> 2) & 1));
#pragma unroll
            for (int nf = 0; nf < 8; nf++) {
                int pig = warpN * 64 + nf * 8 + 2 * tig;     // 0..255 grid px
                int a = a0 + (pig >> 5);
                int b = pig & 31;
                int y = 2 * a + dy;
                int x0 = 2 * b + dx, x1 = x0 + 2;
                float v0 = acc[mf][nf][h2 * 2 + 0] * inv + bias + ns * nzb[y * HO + x0];
                float v1 = acc[mf][nf][h2 * 2 + 1] * inv + bias + ns * nzb[y * HO + x1];
                v0 = v0 > 0.f ? v0 : 0.2f * v0;
                v1 = v1 > 0.f ? v1 : 0.2f * v1;
                hb[((size_t)(y + 1) * 66 + (x0 + 1)) * 512 + ocpos] = tf32r(v0 * sc);
                hb[((size_t)(y + 1) * 66 + (x1 + 1)) * 512 + ocpos] = tf32r(v1 * sc);
            }
        }
    }
}

// ---------------------------------------------------------------------------
// K4b: conv3 GEMM (16-warp version). M=128 oc x N=256 px, K=4608.
// ---------------------------------------------------------------------------
__global__ void __launch_bounds__(NTHR)
k_gemmC(const float* __restrict__ bias_, const float* __restrict__ noise,
        const float* __restrict__ nsp, float* __restrict__ outp) {
    extern __shared__ char sm[];
    const int tid = threadIdx.x;
    const int wid = tid >> 5, lane = tid & 31;
    const int warpM = wid >> 2, warpN = wid & 3;
    const int grp = lane >> 2, tig = lane & 3;

    const int mtile = blockIdx.x;
    const int ocb = mtile << 7;
    const int n_img = blockIdx.y >> 4;
    const int blk = blockIdx.y & 15;
    const int pix0 = blk << 8;
    const int y0 = pix0 >> 6;

    const char* Ablock = (const char*)g_Ac2 + (size_t)mtile * 144 * 16384;
    const char* Bimg = (const char*)g_h1p + (size_t)n_img * (66 * 66 * 512) * 4;
    const uint32_t sb = smem_u32(sm);

    uint32_t pixoff[4], soff[4];
#pragma unroll
    for (int it = 0; it < 4; it++) {
        int c = tid + NTHR * it;
        int nn = c >> 3, r = c & 7;
        int py = y0 + (nn >> 6), px = nn & 63;
        pixoff[it] = (uint32_t)(py * 66 + px) * 2048u + (uint32_t)r * 16u;
        soff[it] = (uint32_t)((r >> 1) * 8192 + nn * 32 + (r & 1) * 16);
    }

    float acc[2][8][4];
#pragma unroll
    for (int a = 0; a < 2; a++)
#pragma unroll
        for (int b = 0; b < 8; b++)
#pragma unroll
            for (int e = 0; e < 4; e++) acc[a][b][e] = 0.f;

    auto load_tile = [&](int kt, int s) {
        uint32_t sa = sb + (uint32_t)s * STAGE_BYTES;
        const char* ag = Ablock + (size_t)kt * 16384;
#pragma unroll
        for (int it = 0; it < 2; it++)
            cpa16(sa + (uint32_t)(tid * 16 + it * 8192), ag + tid * 16 + it * 8192);
        int t = kt >> 4, chunk = kt & 15;
        int dy = t / 3, dx = t - dy * 3;
        const char* bg = Bimg + (dy * 66 + dx) * 2048 + chunk * 128;
        uint32_t sbB = sa + 16384u;
#pragma unroll
        for (int it = 0; it < 4; it++)
            cpa16(sbB + soff[it], bg + pixoff[it]);
        asm volatile("cp.async.commit_group;" ::: "memory");
    };

    load_tile(0, 0);
    load_tile(1, 1);
    load_tile(2, 2);

#pragma unroll 1
    for (int kt = 0; kt < NT; kt++) {
        if (kt < NT - 2)       asm volatile("cp.async.wait_group 2;" ::: "memory");
        else if (kt == NT - 2) asm volatile("cp.async.wait_group 1;" ::: "memory");
        else                   asm volatile("cp.async.wait_group 0;" ::: "memory");
        __syncthreads();

        const char* stg = sm + (kt & 3) * STAGE_BYTES;
        const char* aW = stg;
        const char* bW = stg + 16384 + (warpN * 64 + grp) * 32 + tig * 8;

#pragma unroll
        for (int ks = 0; ks < 4; ks++) {
            uint2 bf[8];
#pragma unroll
            for (int nf = 0; nf < 8; nf++)
                bf[nf] = *(const uint2*)(bW + ks * 8192 + nf * 256);
            uint4 af[2];
#pragma unroll
            for (int mf = 0; mf < 2; mf++)
                af[mf] = *(const uint4*)(aW + ((warpM * 2 + mf) * 4 + ks) * 512 + lane * 16);
#pragma unroll
            for (int mf = 0; mf < 2; mf++)
#pragma unroll
                for (int nf = 0; nf < 8; nf++)
                    mma8(acc[mf][nf], af[mf], bf[nf]);
        }
        if (kt + 3 < NT) load_tile(kt + 3, (kt + 3) & 3);
    }

    const float ns = nsp[0];
#pragma unroll
    for (int mf = 0; mf < 2; mf++) {
#pragma unroll
        for (int h2 = 0; h2 < 2; h2++) {
            int oc = ocb + warpM * 32 + mf * 16 + grp + h2 * 8;
            float inv = 1.f / g_sigma[(1 * NB + n_img) * C + oc];
            float bias = bias_[oc];
#pragma unroll
            for (int nf = 0; nf < 8; nf++) {
                int pix = pix0 + warpN * 64 + nf * 8 + 2 * tig;
                float2 nz = *(const float2*)(noise + (size_t)n_img * PIX + pix);
                float v0 = acc[mf][nf][h2 * 2 + 0] * inv + bias + ns * nz.x;
                float v1 = acc[mf][nf][h2 * 2 + 1] * inv + bias + ns * nz.y;
                v0 = v0 > 0.f ? v0 : 0.2f * v0;
                v1 = v1 > 0.f ? v1 : 0.2f * v1;
                *(float2*)(outp + ((size_t)(n_img * 512 + oc) * PIX) + pix) =
                    make_float2(v0, v1);
            }
        }
    }
}

// ---------------------------------------------------------------------------
// K5: toRGB (1x1 modulated conv, no demod) + lrelu + bilinear 2x skip add
// ---------------------------------------------------------------------------
__device__ __forceinline__ void bl_coords(int Y, int& k0, int& k1, float& w0, float& w1) {
    if (Y & 1) { k0 = (Y - 1) >> 1; k1 = k0 + 1 < 31 ? k0 + 1 : 31; w0 = 0.75f; w1 = 0.25f; }
    else       { int k = Y >> 1; k0 = k - 1 > 0 ? k - 1 : 0; k1 = k; w0 = 0.25f; w1 = 0.75f; }
}

__global__ void k_rgb(const float* __restrict__ yimg, const float* __restrict__ rgb_w,
                      const float* __restrict__ rgb_b, float* __restrict__ out) {
    __shared__ float sw3[3][C];
    const int n = blockIdx.y;
    const int tid = threadIdx.x;
    for (int e = tid; e < 3 * C; e += 256) {
        int c = e >> 9, ci = e & 511;
        sw3[c][ci] = rgb_w[c * C + ci] * g_s[(2 * NB + n) * C + ci];
    }
    __syncthreads();

    const int px = blockIdx.x * 1024 + tid * 4;
    const float* h2 = out + (size_t)n * C * PIX;
    float a0x = 0, a0y = 0, a0z = 0, a0w = 0;
    float a1x = 0, a1y = 0, a1z = 0, a1w = 0;
    float a2x = 0, a2y = 0, a2z = 0, a2w = 0;
#pragma unroll 4
    for (int ci = 0; ci < C; ci++) {
        float4 hv = *(const float4*)(h2 + (size_t)ci * PIX + px);
        float w0 = sw3[0][ci], w1 = sw3[1][ci], w2 = sw3[2][ci];
        a0x = fmaf(hv.x, w0, a0x); a0y = fmaf(hv.y, w0, a0y);
        a0z = fmaf(hv.z, w0, a0z); a0w = fmaf(hv.w, w0, a0w);
        a1x = fmaf(hv.x, w1, a1x); a1y = fmaf(hv.y, w1, a1y);
        a1z = fmaf(hv.z, w1, a1z); a1w = fmaf(hv.w, w1, a1w);
        a2x = fmaf(hv.x, w2, a2x); a2y = fmaf(hv.y, w2, a2y);
        a2z = fmaf(hv.z, w2, a2z); a2w = fmaf(hv.w, w2, a2w);
    }

    float accv[3][4] = {{a0x, a0y, a0z, a0w}, {a1x, a1y, a1z, a1w}, {a2x, a2y, a2z, a2w}};
    const int Y = px >> 6;
    const int X0 = px & 63;
    int ky0, ky1; float wy0, wy1;
    bl_coords(Y, ky0, ky1, wy0, wy1);
    const size_t IMG_OFF = (size_t)NB * C * PIX;

#pragma unroll
    for (int c = 0; c < 3; c++) {
        float bias = rgb_b[c];
        const float* yb = yimg + (size_t)(n * 3 + c) * 32 * 32;
#pragma unroll
        for (int k = 0; k < 4; k++) {
            float r = accv[c][k] + bias;
            r = r > 0.f ? r : 0.2f * r;
            int X = X0 + k;
            int kx0, kx1; float wx0, wx1;
            bl_coords(X, kx0, kx1, wx0, wx1);
            float bv = wy0 * (wx0 * yb[ky0 * 32 + kx0] + wx1 * yb[ky0 * 32 + kx1])
                     + wy1 * (wx0 * yb[ky1 * 32 + kx0] + wx1 * yb[ky1 * 32 + kx1]);
            out[IMG_OFF + (size_t)(n * 3 + c) * PIX + px + k] = bv + r;
        }
    }
}

// ---------------------------------------------------------------------------
extern "C" void kernel_launch(void* const* d_in, const int* in_sizes, int n_in,
                              void* d_out, int out_size) {
    const float* x       = (const float*)d_in[0];
    const float* v       = (const float*)d_in[1];
    const float* yimg    = (const float*)d_in[2];
    const float* noise1  = (const float*)d_in[3];
    const float* noise2  = (const float*)d_in[4];
    const float* up_w    = (const float*)d_in[5];
    const float* up_b    = (const float*)d_in[6];
    const float* up_sw   = (const float*)d_in[7];
    const float* up_sb   = (const float*)d_in[8];
    const float* c_w     = (const float*)d_in[9];
    const float* c_b     = (const float*)d_in[10];
    const float* c_sw    = (const float*)d_in[11];
    const float* c_sb    = (const float*)d_in[12];
    const float* rgb_w   = (const float*)d_in[13];
    const float* rgb_b   = (const float*)d_in[14];
    const float* rgb_sw  = (const float*)d_in[15];
    const float* rgb_sb  = (const float*)d_in[16];
    const float* nsp     = (const float*)d_in[17];
    float* out = (float*)d_out;

    const int SMEM_GEMM = 4 * STAGE_BYTES;   // 192KB
    cudaFuncSetAttribute(k_gemmU, cudaFuncAttributeMaxDynamicSharedMemorySize, SMEM_GEMM);
    cudaFuncSetAttribute(k_gemmC, cudaFuncAttributeMaxDynamicSharedMemorySize, SMEM_GEMM);

    k_style<<<dim3(NB, 3), C>>>(v, up_sw, up_sb, c_sw, c_sb, rgb_sw, rgb_sb);
    k_wsq<<<2048, 256>>>(up_w, c_w);
    k_sigma<<<dim3(NB, 2), C>>>();
    k_modx<<<4357, 256>>>(x);
    k_prepA2<<<18432, 256>>>(up_w, c_w);
    k_halo<<<1040, 256>>>();
    k_gemmU<<<dim3(4, 32, 4), NTHR, SMEM_GEMM>>>(up_b, noise1, nsp);
    k_gemmC<<<dim3(4, 128), NTHR, SMEM_GEMM>>>(c_b, noise2, nsp, out);
    k_rgb<<<dim3(4, NB), 256>>>(yimg, rgb_w, rgb_b, out);
}

// round 11
// speedup vs baseline: 7.4679x; 1.6160x over previous
#include <cuda_runtime.h>
#include <cuda_fp16.h>
#include <cstdint>
#include <math.h>

#define NB 8
#define C 512
#define HO 64
#define PIX 4096
#define NT 72             // conv3: K tiles of 64

// ---------------- device scratch ------------------------------------------
// modulated x, fp16 channels-last with per-16 k-perm, padded 33x33
__device__ __align__(128) __half g_xp[(size_t)NB * 33 * 33 * 512];
// upconv out (modulated for conv3), fp16 channels-last perm, padded 66x66
__device__ __align__(128) __half g_h1p[(size_t)NB * 66 * 66 * 512];
// fragment-layout fp16 weights: [mtile4][kt72][kg4][mf8][lane32][e8]
__device__ __align__(128) __half g_Ac2[(size_t)4 * 72 * 8192];
__device__ __align__(128) __half g_Au2[(size_t)4 * 72 * 8192];
__device__ float g_wsq_up[C * C];
__device__ float g_wsq_cT[C * C];
__device__ float g_s[3 * NB * C];
__device__ float g_sigma[2 * NB * C];

// subpixel class tables (ktile64 units)
__constant__ int c_T[9]  = {4, 3, 5, 1, 7, 0, 2, 6, 8};  // tap into up_w [ky*3+kx]
__constant__ int c_OY[9] = {0, 0, 0, 1, 0, 1, 1, 0, 0};
__constant__ int c_OX[9] = {0, 1, 0, 0, 0, 1, 0, 1, 0};
__constant__ int c_KTB[4] = {0, 8, 24, 40};              // ktile base per class
__constant__ int c_NTC[4] = {8, 16, 16, 32};             // ktile count per class

// per-16 channel position for fp16 k16 fragments:
// pos(c) = ((c>>1)&3)*4 + ((c>>3)&1)*2 + (c&1)  (+ c&~15)
__device__ __forceinline__ int pos16(int c) {
    return (c & ~15) | ((((c >> 1) & 3) << 2) | (((c >> 3) & 1) << 1) | (c & 1));
}

// ---------------- helpers --------------------------------------------------
__device__ __forceinline__ uint32_t smem_u32(const void* p) {
    uint32_t a;
    asm("{ .reg .u64 t; cvta.to.shared.u64 t, %1; cvt.u32.u64 %0, t; }" : "=r"(a) : "l"(p));
    return a;
}
__device__ __forceinline__ void cpa16(uint32_t s, const void* g) {
    asm volatile("cp.async.cg.shared.global [%0], [%1], 16;" :: "r"(s), "l"(g));
}
__device__ __forceinline__ void mma16(float* c, uint4 a, uint2 b) {
    asm volatile("mma.sync.aligned.m16n8k16.row.col.f32.f16.f16.f32 "
        "{%0,%1,%2,%3},{%4,%5,%6,%7},{%8,%9},{%0,%1,%2,%3};"
        : "+f"(c[0]), "+f"(c[1]), "+f"(c[2]), "+f"(c[3])
        : "r"(a.x), "r"(a.y), "r"(a.z), "r"(a.w), "r"(b.x), "r"(b.y));
}

// ---------------------------------------------------------------------------
// K0: weight-square tap sums (fp32 exact, for demod sigma)
// ---------------------------------------------------------------------------
__global__ void k_wsq(const float* __restrict__ up_w, const float* __restrict__ c_w) {
    int idx = blockIdx.x * blockDim.x + threadIdx.x;
    int which = idx >> 18;
    int p = idx & 262143;
    int i = p >> 9, o = p & 511;
    const float* src = which == 0 ? (up_w + ((i << 9) + o) * 9)
                                  : (c_w + ((o << 9) + i) * 9);
    float s = 0.f;
#pragma unroll
    for (int t = 0; t < 9; t++) s += src[t] * src[t];
    if (which == 0) g_wsq_up[p] = s;
    else            g_wsq_cT[p] = s;
}

// ---------------------------------------------------------------------------
// K1: style vectors s = v @ SW + SB
// ---------------------------------------------------------------------------
__global__ void k_style(const float* __restrict__ v,
                        const float* __restrict__ up_sw, const float* __restrict__ up_sb,
                        const float* __restrict__ c_sw,  const float* __restrict__ c_sb,
                        const float* __restrict__ rgb_sw,const float* __restrict__ rgb_sb) {
    int m = blockIdx.y, n = blockIdx.x, i = threadIdx.x;
    __shared__ float sv[C];
    sv[i] = v[n * C + i];
    __syncthreads();
    const float* SW = (m == 0) ? up_sw : (m == 1) ? c_sw : rgb_sw;
    const float* SB = (m == 0) ? up_sb : (m == 1) ? c_sb : rgb_sb;
    float acc = SB[i];
#pragma unroll 4
    for (int l = 0; l < C; l++) acc = fmaf(sv[l], SW[l * C + i], acc);
    g_s[(m * NB + n) * C + i] = acc;
}

// ---------------------------------------------------------------------------
// K2: demod sigma
// ---------------------------------------------------------------------------
__global__ void k_sigma(void) {
    int m = blockIdx.y, n = blockIdx.x, o = threadIdx.x;
    __shared__ float s2[C];
    float sv = g_s[(m * NB + n) * C + o];
    s2[o] = sv * sv;
    __syncthreads();
    const float* wsq = (m == 0) ? g_wsq_up : g_wsq_cT;
    float acc = 1e-8f;
#pragma unroll 4
    for (int i = 0; i < C; i++) acc = fmaf(s2[i], wsq[i * C + o], acc);
    g_sigma[(m * NB + n) * C + o] = sqrtf(acc);
}

// ---------------------------------------------------------------------------
// K3: modulated x -> g_xp fp16 channels-last (per-16 k-perm), 33x33 pad.
// Thread writes 4 halves (positions sub*4..+3 of a 16-group) =
// channels {sub*2, sub*2+1, sub*2+8, sub*2+9} + g*16.
// ---------------------------------------------------------------------------
__global__ void k_modx(const float* __restrict__ x) {
    int idx = blockIdx.x * 256 + threadIdx.x;     // over 8*1089*128
    if (idx >= NB * 1089 * 128) return;
    int sub = idx & 3;
    int g = (idx >> 2) & 31;
    int cell = (idx >> 7) % 1089;
    int nn = (idx >> 7) / 1089;
    int yz = cell / 33, xz = cell % 33;
    __half2 lo = __floats2half2_rn(0.f, 0.f), hi = lo;
    if (yz < 32 && xz < 32) {
        int c0 = g * 16 + sub * 2;
        const float* sp = g_s + (0 * NB + nn) * C;
        const float* xp = x + (((size_t)nn * 512) * 32 + yz) * 32 + xz;
        lo = __floats2half2_rn(xp[(size_t)c0 * 1024] * sp[c0],
                               xp[(size_t)(c0 + 1) * 1024] * sp[c0 + 1]);
        hi = __floats2half2_rn(xp[(size_t)(c0 + 8) * 1024] * sp[c0 + 8],
                               xp[(size_t)(c0 + 9) * 1024] * sp[c0 + 9]);
    }
    __half2* dst = (__half2*)g_xp;
    dst[((size_t)(nn * 1089 + cell) * 512 + g * 16 + sub * 4) >> 1] = lo;
    dst[(((size_t)(nn * 1089 + cell) * 512 + g * 16 + sub * 4) >> 1) + 1] = hi;
}

// ---------------------------------------------------------------------------
// K3b: zero the halo of g_h1p (fp16, 8 halves per uint4)
// ---------------------------------------------------------------------------
__global__ void k_halo(void) {
    int idx = blockIdx.x * 256 + threadIdx.x;   // 8*260*64 = 133120
    if (idx >= NB * 260 * 64) return;
    int ci8 = idx & 63;
    int c2 = idx >> 6;
    int h = c2 % 260, nn = c2 / 260;
    int yz, xz;
    if (h < 66)       { yz = 0;  xz = h; }
    else if (h < 132) { yz = 65; xz = h - 66; }
    else { int rem = h - 132; yz = 1 + (rem >> 1); xz = (rem & 1) * 65; }
    ((uint4*)g_h1p)[((size_t)(nn * 66 + yz) * 66 + xz) * 64 + ci8] =
        make_uint4(0, 0, 0, 0);
}

// ---------------------------------------------------------------------------
// K3c: weights -> fp16 fragment layout.
//   half off = ((((mtile*72+kt)*4+kg)*8+mf)*32+lane)*8 + e
//   reg = e>>1, h = e&1: m = mf*16+grp+(reg&1)*8 ; klocal = tig*2+h+(reg>>1)*8
//   conv3 : kglob = kt*64+kg*16+klocal ; t = kglob>>9 ; ci = kglob&511
//   upconv: tapidx = kt>>3 ; ci = (kt&7)*64+kg*16+klocal ; tap c_T[tapidx]
// ---------------------------------------------------------------------------
#define AFRAG_ELEMS 2359296
__global__ void k_prepA2(const float* __restrict__ up_w, const float* __restrict__ c_w) {
    int idx = blockIdx.x * 256 + threadIdx.x;   // 0 .. 2*2359296
    int which = idx >= AFRAG_ELEMS;
    int off = which ? idx - AFRAG_ELEMS : idx;
    int e = off & 7, lane = (off >> 3) & 31;
    int mf = (off >> 8) & 7, kg = (off >> 11) & 3;
    int rest = off >> 13;
    int kt = rest % 72, mtile = rest / 72;
    int grp = lane >> 2, tig = lane & 3;
    int reg = e >> 1, h = e & 1;
    int m = mf * 16 + grp + (reg & 1) * 8;
    int klocal = tig * 2 + h + (reg >> 1) * 8;
    int oc = mtile * 128 + m;
    float w;
    if (which) {
        int tapidx = kt >> 3;
        int ci = (kt & 7) * 64 + kg * 16 + klocal;
        w = up_w[((size_t)ci * 512 + oc) * 9 + c_T[tapidx]];
    } else {
        int kglob = kt * 64 + kg * 16 + klocal;
        int t = kglob >> 9, ci = kglob & 511;
        w = c_w[((size_t)oc * 512 + ci) * 9 + t];
    }
    __half val = __float2half_rn(w);
    if (which) g_Au2[off] = val;
    else       g_Ac2[off] = val;
}

#define STAGE_BYTES 49152   // 16KB A + 32KB B (K-tile 64, fp16)
#define NTHR 512            // 16 warps: 4 M x 4 N, warp tile 32x64

// ---------------------------------------------------------------------------
// K4a: upconv subpixel GEMM, fp16. blockIdx: (mtile4, img8 x Nblk4, class4).
// ---------------------------------------------------------------------------
__global__ void __launch_bounds__(NTHR)
k_gemmU(const float* __restrict__ bias_, const float* __restrict__ noise,
        const float* __restrict__ nsp) {
    extern __shared__ char sm[];
    const int tid = threadIdx.x;
    const int wid = tid >> 5, lane = tid & 31;
    const int warpM = wid >> 2, warpN = wid & 3;
    const int grp = lane >> 2, tig = lane & 3;

    const int mtile = blockIdx.x;
    const int ocb = mtile << 7;
    const int n_img = blockIdx.y >> 2;
    const int a0 = (blockIdx.y & 3) * 8;
    const int cls = blockIdx.z;
    const int dy = cls >> 1, dx = cls & 1;
    const int ktb = c_KTB[cls];
    const int NTc = c_NTC[cls];

    const char* Ablock = (const char*)g_Au2 + (size_t)mtile * 72 * 16384;
    const char* Bimg = (const char*)g_xp + (size_t)n_img * (33 * 33 * 512) * 2;
    const uint32_t sb = smem_u32(sm);

    uint32_t pixoff[4], soff[4];
#pragma unroll
    for (int it = 0; it < 4; it++) {
        int c = tid + NTHR * it;
        int nn = c >> 3, r = c & 7;
        int py = a0 + (nn >> 5), px = nn & 31;
        pixoff[it] = (uint32_t)(py * 33 + px) * 1024u + (uint32_t)r * 16u;
        soff[it] = (uint32_t)((r >> 1) * 8192 + nn * 32 + (r & 1) * 16);
    }

    float acc[2][8][4];
#pragma unroll
    for (int a = 0; a < 2; a++)
#pragma unroll
        for (int b = 0; b < 8; b++)
#pragma unroll
            for (int e = 0; e < 4; e++) acc[a][b][e] = 0.f;

    auto load_tile = [&](int ktl, int s) {
        int kt = ktb + ktl;
        uint32_t sa = sb + (uint32_t)s * STAGE_BYTES;
        const char* ag = Ablock + (size_t)kt * 16384;
#pragma unroll
        for (int it = 0; it < 2; it++)
            cpa16(sa + (uint32_t)(tid * 16 + it * 8192), ag + tid * 16 + it * 8192);
        int tapidx = kt >> 3, chunk = kt & 7;
        const char* bg = Bimg + (c_OY[tapidx] * 33 + c_OX[tapidx]) * 1024 + chunk * 128;
        uint32_t sbB = sa + 16384u;
#pragma unroll
        for (int it = 0; it < 4; it++)
            cpa16(sbB + soff[it], bg + pixoff[it]);
        asm volatile("cp.async.commit_group;" ::: "memory");
    };

    load_tile(0, 0);
    load_tile(1, 1);
    load_tile(2, 2);

#pragma unroll 1
    for (int kt = 0; kt < NTc; kt++) {
        if (kt < NTc - 2)       asm volatile("cp.async.wait_group 2;" ::: "memory");
        else if (kt == NTc - 2) asm volatile("cp.async.wait_group 1;" ::: "memory");
        else                    asm volatile("cp.async.wait_group 0;" ::: "memory");
        __syncthreads();

        const char* stg = sm + (kt & 3) * STAGE_BYTES;
        const char* bW = stg + 16384 + (warpN * 64 + grp) * 32 + tig * 8;

#pragma unroll
        for (int kg = 0; kg < 4; kg++) {
            uint2 bf[8];
#pragma unroll
            for (int nf = 0; nf < 8; nf++)
                bf[nf] = *(const uint2*)(bW + kg * 8192 + nf * 256);
            uint4 af[2];
#pragma unroll
            for (int mf = 0; mf < 2; mf++)
                af[mf] = *(const uint4*)(stg + kg * 4096 + (warpM * 2 + mf) * 512 + lane * 16);
#pragma unroll
            for (int mf = 0; mf < 2; mf++)
#pragma unroll
                for (int nf = 0; nf < 8; nf++)
                    mma16(acc[mf][nf], af[mf], bf[nf]);
        }
        if (kt + 3 < NTc) load_tile(kt + 3, (kt + 3) & 3);
    }

    // ---------------- epilogue: scatter to parity class ----------------
    const float ns = nsp[0];
    __half* hb = g_h1p + (size_t)n_img * (66 * 66 * 512);
    const float* nzb = noise + (size_t)n_img * PIX;
#pragma unroll
    for (int mf = 0; mf < 2; mf++) {
#pragma unroll
        for (int h2 = 0; h2 < 2; h2++) {
            int oc = ocb + warpM * 32 + mf * 16 + grp + h2 * 8;
            float inv = 1.f / g_sigma[(0 * NB + n_img) * C + oc];
            float bias = bias_[oc];
            float sc = g_s[(1 * NB + n_img) * C + oc];
            int ocpos = pos16(oc);
#pragma unroll
            for (int nf = 0; nf < 8; nf++) {
                int pig = warpN * 64 + nf * 8 + 2 * tig;
                int a = a0 + (pig >> 5);
                int b = pig & 31;
                int y = 2 * a + dy;
                int x0 = 2 * b + dx, x1 = x0 + 2;
                float v0 = acc[mf][nf][h2 * 2 + 0] * inv + bias + ns * nzb[y * HO + x0];
                float v1 = acc[mf][nf][h2 * 2 + 1] * inv + bias + ns * nzb[y * HO + x1];
                v0 = v0 > 0.f ? v0 : 0.2f * v0;
                v1 = v1 > 0.f ? v1 : 0.2f * v1;
                hb[((size_t)(y + 1) * 66 + (x0 + 1)) * 512 + ocpos] = __float2half_rn(v0 * sc);
                hb[((size_t)(y + 1) * 66 + (x1 + 1)) * 512 + ocpos] = __float2half_rn(v1 * sc);
            }
        }
    }
}

// ---------------------------------------------------------------------------
// K4b: conv3 GEMM, fp16. M=128 oc x N=256 px, K=4608 (72 ktile64).
// ---------------------------------------------------------------------------
__global__ void __launch_bounds__(NTHR)
k_gemmC(const float* __restrict__ bias_, const float* __restrict__ noise,
        const float* __restrict__ nsp, float* __restrict__ outp) {
    extern __shared__ char sm[];
    const int tid = threadIdx.x;
    const int wid = tid >> 5, lane = tid & 31;
    const int warpM = wid >> 2, warpN = wid & 3;
    const int grp = lane >> 2, tig = lane & 3;

    const int mtile = blockIdx.x;
    const int ocb = mtile << 7;
    const int n_img = blockIdx.y >> 4;
    const int blk = blockIdx.y & 15;
    const int pix0 = blk << 8;
    const int y0 = pix0 >> 6;

    const char* Ablock = (const char*)g_Ac2 + (size_t)mtile * 72 * 16384;
    const char* Bimg = (const char*)g_h1p + (size_t)n_img * (66 * 66 * 512) * 2;
    const uint32_t sb = smem_u32(sm);

    uint32_t pixoff[4], soff[4];
#pragma unroll
    for (int it = 0; it < 4; it++) {
        int c = tid + NTHR * it;
        int nn = c >> 3, r = c & 7;
        int py = y0 + (nn >> 6), px = nn & 63;
        pixoff[it] = (uint32_t)(py * 66 + px) * 1024u + (uint32_t)r * 16u;
        soff[it] = (uint32_t)((r >> 1) * 8192 + nn * 32 + (r & 1) * 16);
    }

    float acc[2][8][4];
#pragma unroll
    for (int a = 0; a < 2; a++)
#pragma unroll
        for (int b = 0; b < 8; b++)
#pragma unroll
            for (int e = 0; e < 4; e++) acc[a][b][e] = 0.f;

    auto load_tile = [&](int kt, int s) {
        uint32_t sa = sb + (uint32_t)s * STAGE_BYTES;
        const char* ag = Ablock + (size_t)kt * 16384;
#pragma unroll
        for (int it = 0; it < 2; it++)
            cpa16(sa + (uint32_t)(tid * 16 + it * 8192), ag + tid * 16 + it * 8192);
        int t = kt >> 3, chunk = kt & 7;
        int dy = t / 3, dx = t - dy * 3;
        const char* bg = Bimg + (dy * 66 + dx) * 1024 + chunk * 128;
        uint32_t sbB = sa + 16384u;
#pragma unroll
        for (int it = 0; it < 4; it++)
            cpa16(sbB + soff[it], bg + pixoff[it]);
        asm volatile("cp.async.commit_group;" ::: "memory");
    };

    load_tile(0, 0);
    load_tile(1, 1);
    load_tile(2, 2);

#pragma unroll 1
    for (int kt = 0; kt < NT; kt++) {
        if (kt < NT - 2)       asm volatile("cp.async.wait_group 2;" ::: "memory");
        else if (kt == NT - 2) asm volatile("cp.async.wait_group 1;" ::: "memory");
        else                   asm volatile("cp.async.wait_group 0;" ::: "memory");
        __syncthreads();

        const char* stg = sm + (kt & 3) * STAGE_BYTES;
        const char* bW = stg + 16384 + (warpN * 64 + grp) * 32 + tig * 8;

#pragma unroll
        for (int kg = 0; kg < 4; kg++) {
            uint2 bf[8];
#pragma unroll
            for (int nf = 0; nf < 8; nf++)
                bf[nf] = *(const uint2*)(bW + kg * 8192 + nf * 256);
            uint4 af[2];
#pragma unroll
            for (int mf = 0; mf < 2; mf++)
                af[mf] = *(const uint4*)(stg + kg * 4096 + (warpM * 2 + mf) * 512 + lane * 16);
#pragma unroll
            for (int mf = 0; mf < 2; mf++)
#pragma unroll
                for (int nf = 0; nf < 8; nf++)
                    mma16(acc[mf][nf], af[mf], bf[nf]);
        }
        if (kt + 3 < NT) load_tile(kt + 3, (kt + 3) & 3);
    }

    const float ns = nsp[0];
#pragma unroll
    for (int mf = 0; mf < 2; mf++) {
#pragma unroll
        for (int h2 = 0; h2 < 2; h2++) {
            int oc = ocb + warpM * 32 + mf * 16 + grp + h2 * 8;
            float inv = 1.f / g_sigma[(1 * NB + n_img) * C + oc];
            float bias = bias_[oc];
#pragma unroll
            for (int nf = 0; nf < 8; nf++) {
                int pix = pix0 + warpN * 64 + nf * 8 + 2 * tig;
                float2 nz = *(const float2*)(noise + (size_t)n_img * PIX + pix);
                float v0 = acc[mf][nf][h2 * 2 + 0] * inv + bias + ns * nz.x;
                float v1 = acc[mf][nf][h2 * 2 + 1] * inv + bias + ns * nz.y;
                v0 = v0 > 0.f ? v0 : 0.2f * v0;
                v1 = v1 > 0.f ? v1 : 0.2f * v1;
                *(float2*)(outp + ((size_t)(n_img * 512 + oc) * PIX) + pix) =
                    make_float2(v0, v1);
            }
        }
    }
}

// ---------------------------------------------------------------------------
// K5: toRGB (1x1 modulated conv, no demod) + lrelu + bilinear 2x skip add
// ---------------------------------------------------------------------------
__device__ __forceinline__ void bl_coords(int Y, int& k0, int& k1, float& w0, float& w1) {
    if (Y & 1) { k0 = (Y - 1) >> 1; k1 = k0 + 1 < 31 ? k0 + 1 : 31; w0 = 0.75f; w1 = 0.25f; }
    else       { int k = Y >> 1; k0 = k - 1 > 0 ? k - 1 : 0; k1 = k; w0 = 0.25f; w1 = 0.75f; }
}

__global__ void k_rgb(const float* __restrict__ yimg, const float* __restrict__ rgb_w,
                      const float* __restrict__ rgb_b, float* __restrict__ out) {
    __shared__ float sw3[3][C];
    const int n = blockIdx.y;
    const int tid = threadIdx.x;
    for (int e = tid; e < 3 * C; e += 256) {
        int c = e >> 9, ci = e & 511;
        sw3[c][ci] = rgb_w[c * C + ci] * g_s[(2 * NB + n) * C + ci];
    }
    __syncthreads();

    const int px = blockIdx.x * 1024 + tid * 4;
    const float* h2 = out + (size_t)n * C * PIX;
    float a0x = 0, a0y = 0, a0z = 0, a0w = 0;
    float a1x = 0, a1y = 0, a1z = 0, a1w = 0;
    float a2x = 0, a2y = 0, a2z = 0, a2w = 0;
#pragma unroll 4
    for (int ci = 0; ci < C; ci++) {
        float4 hv = *(const float4*)(h2 + (size_t)ci * PIX + px);
        float w0 = sw3[0][ci], w1 = sw3[1][ci], w2 = sw3[2][ci];
        a0x = fmaf(hv.x, w0, a0x); a0y = fmaf(hv.y, w0, a0y);
        a0z = fmaf(hv.z, w0, a0z); a0w = fmaf(hv.w, w0, a0w);
        a1x = fmaf(hv.x, w1, a1x); a1y = fmaf(hv.y, w1, a1y);
        a1z = fmaf(hv.z, w1, a1z); a1w = fmaf(hv.w, w1, a1w);
        a2x = fmaf(hv.x, w2, a2x); a2y = fmaf(hv.y, w2, a2y);
        a2z = fmaf(hv.z, w2, a2z); a2w = fmaf(hv.w, w2, a2w);
    }

    float accv[3][4] = {{a0x, a0y, a0z, a0w}, {a1x, a1y, a1z, a1w}, {a2x, a2y, a2z, a2w}};
    const int Y = px >> 6;
    const int X0 = px & 63;
    int ky0, ky1; float wy0, wy1;
    bl_coords(Y, ky0, ky1, wy0, wy1);
    const size_t IMG_OFF = (size_t)NB * C * PIX;

#pragma unroll
    for (int c = 0; c < 3; c++) {
        float bias = rgb_b[c];
        const float* yb = yimg + (size_t)(n * 3 + c) * 32 * 32;
#pragma unroll
        for (int k = 0; k < 4; k++) {
            float r = accv[c][k] + bias;
            r = r > 0.f ? r : 0.2f * r;
            int X = X0 + k;
            int kx0, kx1; float wx0, wx1;
            bl_coords(X, kx0, kx1, wx0, wx1);
            float bv = wy0 * (wx0 * yb[ky0 * 32 + kx0] + wx1 * yb[ky0 * 32 + kx1])
                     + wy1 * (wx0 * yb[ky1 * 32 + kx0] + wx1 * yb[ky1 * 32 + kx1]);
            out[IMG_OFF + (size_t)(n * 3 + c) * PIX + px + k] = bv + r;
        }
    }
}

// ---------------------------------------------------------------------------
extern "C" void kernel_launch(void* const* d_in, const int* in_sizes, int n_in,
                              void* d_out, int out_size) {
    const float* x       = (const float*)d_in[0];
    const float* v       = (const float*)d_in[1];
    const float* yimg    = (const float*)d_in[2];
    const float* noise1  = (const float*)d_in[3];
    const float* noise2  = (const float*)d_in[4];
    const float* up_w    = (const float*)d_in[5];
    const float* up_b    = (const float*)d_in[6];
    const float* up_sw   = (const float*)d_in[7];
    const float* up_sb   = (const float*)d_in[8];
    const float* c_w     = (const float*)d_in[9];
    const float* c_b     = (const float*)d_in[10];
    const float* c_sw    = (const float*)d_in[11];
    const float* c_sb    = (const float*)d_in[12];
    const float* rgb_w   = (const float*)d_in[13];
    const float* rgb_b   = (const float*)d_in[14];
    const float* rgb_sw  = (const float*)d_in[15];
    const float* rgb_sb  = (const float*)d_in[16];
    const float* nsp     = (const float*)d_in[17];
    float* out = (float*)d_out;

    const int SMEM_GEMM = 4 * STAGE_BYTES;   // 192KB
    cudaFuncSetAttribute(k_gemmU, cudaFuncAttributeMaxDynamicSharedMemorySize, SMEM_GEMM);
    cudaFuncSetAttribute(k_gemmC, cudaFuncAttributeMaxDynamicSharedMemorySize, SMEM_GEMM);

    k_style<<<dim3(NB, 3), C>>>(v, up_sw, up_sb, c_sw, c_sb, rgb_sw, rgb_sb);
    k_wsq<<<2048, 256>>>(up_w, c_w);
    k_sigma<<<dim3(NB, 2), C>>>();
    k_modx<<<4356, 256>>>(x);
    k_prepA2<<<18432, 256>>>(up_w, c_w);
    k_halo<<<520, 256>>>();
    k_gemmU<<<dim3(4, 32, 4), NTHR, SMEM_GEMM>>>(up_b, noise1, nsp);
    k_gemmC<<<dim3(4, 128), NTHR, SMEM_GEMM>>>(c_b, noise2, nsp, out);
    k_rgb<<<dim3(4, NB), 256>>>(yimg, rgb_w, rgb_b, out);
}